// round 10
// baseline (speedup 1.0000x reference)
#include <cuda_runtime.h>
#include <cuda_bf16.h>
#include <math.h>
#include <stdint.h>

#define Nn 50000
#define Ee 400000
#define Pp 3

// ---------------- scratch (device globals) --------------------------------------
__device__ __align__(16) __nv_bfloat16 g_x_hi[(size_t)Nn * 128];
__device__ __align__(16) __nv_bfloat16 g_x_lo[(size_t)Nn * 128];
__device__ __align__(16) float g_feat[(size_t)Pp * Nn * 128];
__device__ __align__(16) __nv_bfloat16 g_z_hi[(size_t)Pp * Nn * 128];
__device__ __align__(16) __nv_bfloat16 g_z_lo[(size_t)Pp * Nn * 128];
__device__ __align__(16) float g_el[(size_t)Pp * Nn * 4];
__device__ __align__(16) float g_er[(size_t)Pp * Nn * 4];
__device__ int g_deg[(size_t)Pp * Nn];
__device__ int g_off[(size_t)Pp * (Nn + 1)];
__device__ int g_cur[(size_t)Pp * Nn];
__device__ int g_csrc[(size_t)Pp * Ee];
__device__ __align__(16) __nv_bfloat16 g_bt_hi[4 * 128 * 128];
__device__ __align__(16) __nv_bfloat16 g_bt_lo[4 * 128 * 128];
__device__ float g_wsem[Pp];
__device__ float g_bsem[Pp];

// ---------------- smem layout ------------------------------------------------------
#define SROW 72
#define TILEB (128 * SROW * 2)
#define S_AUX0 0
#define S_AUX1 512
#define S_RED  1024
#define S_A0H  2048
#define S_A0L  (S_A0H + TILEB)
#define S_A1H  (S_A0L + TILEB)
#define S_A1L  (S_A1H + TILEB)
#define S_BH   (S_A1L + TILEB)
#define S_BL   (S_BH + TILEB)
#define SMEM_TOT (S_BL + TILEB)       // 112640
#define SDW 132

__device__ __forceinline__ void mma16816(float& d0, float& d1, float& d2, float& d3,
                                         uint32_t a0, uint32_t a1, uint32_t a2, uint32_t a3,
                                         uint32_t b0, uint32_t b1) {
    asm volatile(
        "mma.sync.aligned.m16n8k16.row.col.f32.bf16.bf16.f32 "
        "{%0,%1,%2,%3}, {%4,%5,%6,%7}, {%8,%9}, {%0,%1,%2,%3};"
        : "+f"(d0), "+f"(d1), "+f"(d2), "+f"(d3)
        : "r"(a0), "r"(a1), "r"(a2), "r"(a3), "r"(b0), "r"(b1));
}

__device__ __forceinline__ void ldsm4(uint32_t& r0, uint32_t& r1, uint32_t& r2,
                                      uint32_t& r3, uint32_t addr) {
    asm volatile("ldmatrix.sync.aligned.m8n8.x4.shared.b16 {%0,%1,%2,%3}, [%4];"
                 : "=r"(r0), "=r"(r1), "=r"(r2), "=r"(r3) : "r"(addr));
}

__device__ __forceinline__ void cpa16(uint32_t dst, const void* src, int sz) {
    asm volatile("cp.async.cg.shared.global [%0], [%1], 16, %2;"
                 :: "r"(dst), "l"(src), "r"(sz));
}
#define CP_COMMIT() asm volatile("cp.async.commit_group;" ::: "memory")
#define CP_WAIT(n)  asm volatile("cp.async.wait_group %0;" :: "n"(n) : "memory")

template <bool FULL>
__device__ __forceinline__ void fill_A(uint32_t sbase, const __nv_bfloat16* ah,
                                       const __nv_bfloat16* al, int n0, int slab, int tid) {
    const int ITS = FULL ? 8 : 4;
#pragma unroll
    for (int it = 0; it < ITS; it++) {
        int idx = it * 256 + tid;
        int prec = idx >> 10;
        int rem = idx & 1023;
        int row = rem >> 3;
        int ch = rem & 7;
        int n = n0 + row;
        int nc = n < Nn ? n : Nn - 1;
        const __nv_bfloat16* s = (prec ? al : ah) + (size_t)nc * 128 + slab * 64 + ch * 8;
        uint32_t d = sbase + (uint32_t)(prec * TILEB + (row * SROW + ch * 8) * 2);
        cpa16(d, s, n < Nn ? 16 : 0);
    }
}

__device__ __forceinline__ void fill_B(uint32_t sbase, const __nv_bfloat16* bh,
                                       const __nv_bfloat16* bl, int slab, int tid) {
#pragma unroll
    for (int it = 0; it < 8; it++) {
        int idx = it * 256 + tid;
        int prec = idx >> 10;
        int rem = idx & 1023;
        int row = rem >> 3;
        int ch = rem & 7;
        const __nv_bfloat16* s = (prec ? bl : bh) + (size_t)row * 128 + slab * 64 + ch * 8;
        uint32_t d = sbase + (uint32_t)(prec * TILEB + (row * SROW + ch * 8) * 2);
        cpa16(d, s, 16);
    }
}

template <bool FULL>
__device__ __forceinline__ void mma_slab(uint32_t smem_s, uint32_t abase, float d[2][8][4],
                                         int lane, int wid) {
    int warpM = wid & 3, warpN = wid >> 2;
    int grp = lane >> 3, lr = lane & 7;
    uint32_t aA = smem_s + abase +
        (uint32_t)(((warpM * 32 + lr + (grp & 1) * 8) * SROW + (grp >> 1) * 8) * 2);
    uint32_t aB = smem_s + S_BH +
        (uint32_t)(((warpN * 64 + lr + (grp >> 1) * 8) * SROW + (grp & 1) * 8) * 2);
    const uint32_t MT = 16 * SROW * 2;

#pragma unroll
    for (int ks = 0; ks < 4; ks++) {
        uint32_t kb = (uint32_t)(ks * 32);
        uint32_t ah[2][4], al[2][4], bb[4][4];
#pragma unroll
        for (int mt = 0; mt < 2; mt++) {
            ldsm4(ah[mt][0], ah[mt][1], ah[mt][2], ah[mt][3], aA + mt * MT + kb);
            if (FULL)
                ldsm4(al[mt][0], al[mt][1], al[mt][2], al[mt][3], aA + TILEB + mt * MT + kb);
        }
#pragma unroll
        for (int np = 0; np < 4; np++)
            ldsm4(bb[np][0], bb[np][1], bb[np][2], bb[np][3], aB + np * MT + kb);
#pragma unroll
        for (int np = 0; np < 4; np++)
#pragma unroll
            for (int mt = 0; mt < 2; mt++) {
                mma16816(d[mt][2 * np][0], d[mt][2 * np][1], d[mt][2 * np][2], d[mt][2 * np][3],
                         ah[mt][0], ah[mt][1], ah[mt][2], ah[mt][3], bb[np][0], bb[np][1]);
                mma16816(d[mt][2 * np + 1][0], d[mt][2 * np + 1][1], d[mt][2 * np + 1][2], d[mt][2 * np + 1][3],
                         ah[mt][0], ah[mt][1], ah[mt][2], ah[mt][3], bb[np][2], bb[np][3]);
            }
        if (FULL) {
#pragma unroll
            for (int np = 0; np < 4; np++)
#pragma unroll
                for (int mt = 0; mt < 2; mt++) {
                    mma16816(d[mt][2 * np][0], d[mt][2 * np][1], d[mt][2 * np][2], d[mt][2 * np][3],
                             al[mt][0], al[mt][1], al[mt][2], al[mt][3], bb[np][0], bb[np][1]);
                    mma16816(d[mt][2 * np + 1][0], d[mt][2 * np + 1][1], d[mt][2 * np + 1][2], d[mt][2 * np + 1][3],
                             al[mt][0], al[mt][1], al[mt][2], al[mt][3], bb[np][2], bb[np][3]);
                }
        }
#pragma unroll
        for (int np = 0; np < 4; np++)
            ldsm4(bb[np][0], bb[np][1], bb[np][2], bb[np][3], aB + TILEB + np * MT + kb);
#pragma unroll
        for (int np = 0; np < 4; np++)
#pragma unroll
            for (int mt = 0; mt < 2; mt++) {
                mma16816(d[mt][2 * np][0], d[mt][2 * np][1], d[mt][2 * np][2], d[mt][2 * np][3],
                         ah[mt][0], ah[mt][1], ah[mt][2], ah[mt][3], bb[np][0], bb[np][1]);
                mma16816(d[mt][2 * np + 1][0], d[mt][2 * np + 1][1], d[mt][2 * np + 1][2], d[mt][2 * np + 1][3],
                         ah[mt][0], ah[mt][1], ah[mt][2], ah[mt][3], bb[np][2], bb[np][3]);
            }
    }
}

template <bool FULL>
__device__ __forceinline__ void gemm_core(const __nv_bfloat16* __restrict__ ah,
                                          const __nv_bfloat16* __restrict__ alo,
                                          int n0,
                                          const __nv_bfloat16* __restrict__ bth,
                                          const __nv_bfloat16* __restrict__ btl,
                                          char* smem, float d[2][8][4]) {
    int tid = threadIdx.x, lane = tid & 31, wid = tid >> 5;
    uint32_t smem_s = (uint32_t)__cvta_generic_to_shared(smem);

    fill_B(smem_s + S_BH, bth, btl, 0, tid);
    fill_A<FULL>(smem_s + S_A0H, ah, alo, n0, 0, tid);
    CP_COMMIT();
    fill_A<FULL>(smem_s + S_A1H, ah, alo, n0, 1, tid);
    CP_COMMIT();
    CP_WAIT(1);
    __syncthreads();
    mma_slab<FULL>(smem_s, S_A0H, d, lane, wid);
    __syncthreads();
    fill_B(smem_s + S_BH, bth, btl, 1, tid);
    CP_COMMIT();
    CP_WAIT(0);
    __syncthreads();
    mma_slab<FULL>(smem_s, S_A1H, d, lane, wid);
    __syncthreads();
}

__device__ __forceinline__ void stage_d(float* sd, float d[2][8][4], int lane, int wid) {
    int warpM = wid & 3, warpN = wid >> 2;
    int rq = lane >> 2, cq = (lane & 3) * 2;
#pragma unroll
    for (int mt = 0; mt < 2; mt++) {
        int rl0 = warpM * 32 + mt * 16 + rq;
        int rl1 = rl0 + 8;
#pragma unroll
        for (int nt = 0; nt < 8; nt++) {
            int c = warpN * 64 + nt * 8 + cq;
            *(float2*)&sd[rl0 * SDW + c] = make_float2(d[mt][nt][0], d[mt][nt][1]);
            *(float2*)&sd[rl1 * SDW + c] = make_float2(d[mt][nt][2], d[mt][nt][3]);
        }
    }
}

// ---------------- projection GEMM + fused el/er -----------------------------------
__global__ void __launch_bounds__(256, 2) k_gemm_feat(
    const __nv_bfloat16* __restrict__ xh, const __nv_bfloat16* __restrict__ xl,
    const __nv_bfloat16* __restrict__ bth, const __nv_bfloat16* __restrict__ btl,
    const float* __restrict__ al, const float* __restrict__ ar,
    float* __restrict__ feat, float* __restrict__ el, float* __restrict__ er) {
    extern __shared__ char smem[];
    int tid = threadIdx.x, lane = tid & 31, wid = tid >> 5;
    int p = blockIdx.y;
    int n0 = blockIdx.x * 128;
    float* sal = (float*)(smem + S_AUX0);
    float* sar = (float*)(smem + S_AUX1);
    if (tid < 128) { sal[tid] = al[p * 128 + tid]; sar[tid] = ar[p * 128 + tid]; }

    float d[2][8][4];
#pragma unroll
    for (int mt = 0; mt < 2; mt++)
#pragma unroll
        for (int nt = 0; nt < 8; nt++)
#pragma unroll
            for (int q = 0; q < 4; q++) d[mt][nt][q] = 0.f;

    gemm_core<true>(xh, xl, n0, bth + (size_t)p * 16384, btl + (size_t)p * 16384, smem, d);

    float* sd = (float*)(smem + S_A0H);
    stage_d(sd, d, lane, wid);
    __syncthreads();

    int row = tid >> 1, half = tid & 1;
    int n = n0 + row;
    if (n < Nn) {
        float sel[2] = {0.f, 0.f}, ser[2] = {0.f, 0.f};
        float4* o = (float4*)&feat[((size_t)p * Nn + n) * 128 + half * 64];
#pragma unroll
        for (int q = 0; q < 16; q++) {
            float4 v = *(float4*)&sd[row * SDW + half * 64 + q * 4];
            o[q] = v;
            int hb = q >> 3;
            int c = half * 64 + q * 4;
            sel[hb] = fmaf(v.x, sal[c + 0], sel[hb]);
            sel[hb] = fmaf(v.y, sal[c + 1], sel[hb]);
            sel[hb] = fmaf(v.z, sal[c + 2], sel[hb]);
            sel[hb] = fmaf(v.w, sal[c + 3], sel[hb]);
            ser[hb] = fmaf(v.x, sar[c + 0], ser[hb]);
            ser[hb] = fmaf(v.y, sar[c + 1], ser[hb]);
            ser[hb] = fmaf(v.z, sar[c + 2], ser[hb]);
            ser[hb] = fmaf(v.w, sar[c + 3], ser[hb]);
        }
        *(float2*)&el[((size_t)p * Nn + n) * 4 + half * 2] = make_float2(sel[0], sel[1]);
        *(float2*)&er[((size_t)p * Nn + n) * 4 + half * 2] = make_float2(ser[0], ser[1]);
    }
}

// ---------------- semantic GEMM (2-pass) + tanh/w2 reduce ---------------------------
__global__ void __launch_bounds__(256, 2) k_semgemm(
    const __nv_bfloat16* __restrict__ zh, const __nv_bfloat16* __restrict__ zl,
    const __nv_bfloat16* __restrict__ bth, const __nv_bfloat16* __restrict__ btl,
    const float* __restrict__ b1, const float* __restrict__ w2, float* __restrict__ wsem) {
    extern __shared__ char smem[];
    int tid = threadIdx.x, lane = tid & 31, wid = tid >> 5;
    int p = blockIdx.y;
    int n0 = blockIdx.x * 128;
    float* sb1 = (float*)(smem + S_AUX0);
    float* sw2 = (float*)(smem + S_AUX1);
    float* sred = (float*)(smem + S_RED);
    if (tid < 128) { sb1[tid] = b1[tid]; sw2[tid] = w2[tid]; }

    float d[2][8][4];
#pragma unroll
    for (int mt = 0; mt < 2; mt++)
#pragma unroll
        for (int nt = 0; nt < 8; nt++)
#pragma unroll
            for (int q = 0; q < 4; q++) d[mt][nt][q] = 0.f;

    gemm_core<false>(zh + (size_t)p * Nn * 128, zl, n0, bth, btl, smem, d);

    float* sd = (float*)(smem + S_A0H);
    stage_d(sd, d, lane, wid);
    __syncthreads();

    int row = tid >> 1, half = tid & 1;
    int n = n0 + row;
    float accv = 0.f;
    if (n < Nn) {
#pragma unroll
        for (int q = 0; q < 16; q++) {
            float4 v = *(float4*)&sd[row * SDW + half * 64 + q * 4];
            int c = half * 64 + q * 4;
            accv = fmaf(tanhf(v.x + sb1[c + 0]), sw2[c + 0], accv);
            accv = fmaf(tanhf(v.y + sb1[c + 1]), sw2[c + 1], accv);
            accv = fmaf(tanhf(v.z + sb1[c + 2]), sw2[c + 2], accv);
            accv = fmaf(tanhf(v.w + sb1[c + 3]), sw2[c + 3], accv);
        }
    }
#pragma unroll
    for (int o = 16; o; o >>= 1) accv += __shfl_xor_sync(0xffffffffu, accv, o);
    if (lane == 0) sred[wid] = accv;
    __syncthreads();
    if (tid == 0) {
        float s = 0.f;
#pragma unroll
        for (int i = 0; i < 8; i++) s += sred[i];
        atomicAdd(&wsem[p], s);
    }
}

// ---------------- feature attention: warp per node ----------------------------------
__global__ void k_featatt(const float* __restrict__ h, const float* __restrict__ cf,
                          const float* __restrict__ w1, const float* __restrict__ b1,
                          const float* __restrict__ w2,
                          __nv_bfloat16* __restrict__ xh, __nv_bfloat16* __restrict__ xl) {
    __shared__ float sw1[42 * 16];
    __shared__ float sb1[16], sw2[16];
    __shared__ __align__(16) float sf[8][840];
    __shared__ float ss[8][20];
    int tid = threadIdx.x, wid = tid >> 5, lane = tid & 31;
    for (int i = tid; i < 672; i += 256) sw1[i] = w1[i];
    if (tid < 16) { sb1[tid] = b1[tid]; sw2[tid] = w2[tid]; }
    __syncthreads();
    int n = blockIdx.x * 8 + wid;
    if (n >= Nn) return;

    const float4* fr4 = (const float4*)(cf + (size_t)n * 840);
    float* myf = sf[wid];
    float4* myf4 = (float4*)myf;
    for (int i = lane; i < 210; i += 32) myf4[i] = fr4[i];
    __syncwarp();

    int k = lane & 15;
    for (int j0 = 0; j0 < 20; j0 += 2) {
        int j = j0 + (lane >> 4);
        const float* fj = myf + j * 42;
        float acc = sb1[k];
#pragma unroll
        for (int i = 0; i < 42; i++) acc = fmaf(fj[i], sw1[i * 16 + k], acc);
        float v = tanhf(acc) * sw2[k];
#pragma unroll
        for (int off = 8; off; off >>= 1) v += __shfl_down_sync(0xffffffffu, v, off);
        if (k == 0) ss[wid][j] = v;
    }
    __syncwarp();

    float sc = (lane < 20) ? ss[wid][lane] : -INFINITY;
    float mx = sc;
#pragma unroll
    for (int off = 16; off; off >>= 1) mx = fmaxf(mx, __shfl_xor_sync(0xffffffffu, mx, off));
    float ex = (lane < 20) ? expf(sc - mx) : 0.f;
    float sm = ex;
#pragma unroll
    for (int off = 16; off; off >>= 1) sm += __shfl_xor_sync(0xffffffffu, sm, off);
    float beta = ex / sm;

    float a0 = 0.f, a1 = 0.f;
    for (int j = 0; j < 20; j++) {
        float bj = __shfl_sync(0xffffffffu, beta, j);
        a0 = fmaf(bj, myf[j * 42 + lane], a0);
        if (lane < 10) a1 = fmaf(bj, myf[j * 42 + 32 + lane], a1);
    }
    const float* hr = h + (size_t)n * 86;
    __nv_bfloat16* xhr = xh + (size_t)n * 128;
    __nv_bfloat16* xlr = xl + (size_t)n * 128;
    for (int i = lane; i < 86; i += 32) {
        float v = hr[i];
        __nv_bfloat16 hh = __float2bfloat16(v);
        xhr[i] = hh;
        xlr[i] = __float2bfloat16(v - __bfloat162float(hh));
    }
    {
        __nv_bfloat16 hh = __float2bfloat16(a0);
        xhr[86 + lane] = hh;
        xlr[86 + lane] = __float2bfloat16(a0 - __bfloat162float(hh));
    }
    if (lane < 10) {
        __nv_bfloat16 hh = __float2bfloat16(a1);
        xhr[118 + lane] = hh;
        xlr[118 + lane] = __float2bfloat16(a1 - __bfloat162float(hh));
    }
}

// ---------------- weight prep ---------------------------------------------------------
__global__ void k_wprep(const float* __restrict__ gatW, const float* __restrict__ saw1,
                        __nv_bfloat16* __restrict__ bh, __nv_bfloat16* __restrict__ bl) {
    int idx = blockIdx.x * 256 + threadIdx.x;
    if (idx >= 4 * 16384) return;
    int slot = idx >> 14, rem = idx & 16383;
    int nIdx = rem >> 7, kIdx = rem & 127;
    float v = (slot < 3) ? gatW[slot * 16384 + kIdx * 128 + nIdx] : saw1[kIdx * 128 + nIdx];
    __nv_bfloat16 hh = __float2bfloat16(v);
    bh[idx] = hh;
    bl[idx] = __float2bfloat16(v - __bfloat162float(hh));
}

// ---------------- CSR build (4-way ILP atomics) ----------------------------------------
__global__ void k_count(const int* __restrict__ dst, int* __restrict__ deg) {
    int p = blockIdx.y;
    int base = blockIdx.x * 1024 + threadIdx.x;
#pragma unroll
    for (int j = 0; j < 4; j++) {
        int e = base + j * 256;
        if (e < Ee) atomicAdd(&deg[(size_t)p * Nn + dst[(size_t)p * Ee + e]], 1);
    }
}

__global__ void k_scan(const int* __restrict__ deg, int* __restrict__ off,
                       int* __restrict__ cur) {
    int p = blockIdx.x;
    int tid = threadIdx.x, lane = tid & 31, wid = tid >> 5;
    __shared__ int wsum[32];
    __shared__ int carry;
    if (tid == 0) carry = 0;
    __syncthreads();
    for (int base = 0; base < Nn; base += 1024) {
        int i = base + tid;
        int v = (i < Nn) ? deg[(size_t)p * Nn + i] : 0;
        int xv = v;
#pragma unroll
        for (int o = 1; o < 32; o <<= 1) {
            int t = __shfl_up_sync(0xffffffffu, xv, o);
            if (lane >= o) xv += t;
        }
        if (lane == 31) wsum[wid] = xv;
        __syncthreads();
        if (wid == 0) {
            int y = wsum[lane];
#pragma unroll
            for (int o = 1; o < 32; o <<= 1) {
                int t = __shfl_up_sync(0xffffffffu, y, o);
                if (lane >= o) y += t;
            }
            wsum[lane] = y;
        }
        __syncthreads();
        int wpre = (wid == 0) ? 0 : wsum[wid - 1];
        int excl = carry + wpre + xv - v;
        if (i < Nn) {
            off[(size_t)p * (Nn + 1) + i] = excl;
            cur[(size_t)p * Nn + i] = excl;
        }
        __syncthreads();
        if (tid == 1023) carry = excl + v;
        __syncthreads();
    }
    if (tid == 0) off[(size_t)p * (Nn + 1) + Nn] = carry;
}

__global__ void k_scatter(const int* __restrict__ src, const int* __restrict__ dst,
                          int* __restrict__ cur, int* __restrict__ csrc) {
    int p = blockIdx.y;
    int base = blockIdx.x * 1024 + threadIdx.x;
    int ev[4], dv[4], sv[4];
#pragma unroll
    for (int j = 0; j < 4; j++) {
        ev[j] = base + j * 256;
        if (ev[j] < Ee) {
            dv[j] = dst[(size_t)p * Ee + ev[j]];
            sv[j] = src[(size_t)p * Ee + ev[j]];
        }
    }
#pragma unroll
    for (int j = 0; j < 4; j++) {
        if (ev[j] < Ee) {
            int pos = atomicAdd(&cur[(size_t)p * Nn + dv[j]], 1);
            csrc[(size_t)p * Ee + pos] = sv[j];
        }
    }
}

// ---------------- gather aggregation: warp per (p, dst), 4-wide edge ILP --------------
__device__ __forceinline__ float4 edge_w(float4 a, float4 er4, float4 mx) {
    float4 w;
    float t;
    t = a.x + er4.x; t = t > 0.f ? t : 0.2f * t; w.x = __expf(t - mx.x);
    t = a.y + er4.y; t = t > 0.f ? t : 0.2f * t; w.y = __expf(t - mx.y);
    t = a.z + er4.z; t = t > 0.f ? t : 0.2f * t; w.z = __expf(t - mx.z);
    t = a.w + er4.w; t = t > 0.f ? t : 0.2f * t; w.w = __expf(t - mx.w);
    return w;
}

__global__ void k_gather(const int* __restrict__ csrc, const int* __restrict__ off,
                         const float* __restrict__ el, const float* __restrict__ er,
                         const float* __restrict__ feat,
                         __nv_bfloat16* __restrict__ zh, __nv_bfloat16* __restrict__ zl) {
    int p = blockIdx.y;
    int tid = threadIdx.x, wid = tid >> 5, lane = tid & 31;
    int n = blockIdx.x * 8 + wid;
    if (n >= Nn) return;
    long r = (long)p * Nn + n;
    int start = off[(size_t)p * (Nn + 1) + n];
    int end = off[(size_t)p * (Nn + 1) + n + 1];
    float4 acc = make_float4(0.f, 0.f, 0.f, 0.f);
    if (start < end) {
        const int* sp = csrc + (size_t)p * Ee;
        const float4* elp = (const float4*)el + (size_t)p * Nn;
        const float* fp = feat + (size_t)p * Nn * 128;
        float4 er4 = ((const float4*)er)[r];

        float4 mx = make_float4(-INFINITY, -INFINITY, -INFINITY, -INFINITY);
        for (int i = start + lane; i < end; i += 32) {
            float4 a = elp[sp[i]];
            float vx = a.x + er4.x; vx = vx > 0.f ? vx : 0.2f * vx;
            float vy = a.y + er4.y; vy = vy > 0.f ? vy : 0.2f * vy;
            float vz = a.z + er4.z; vz = vz > 0.f ? vz : 0.2f * vz;
            float vw = a.w + er4.w; vw = vw > 0.f ? vw : 0.2f * vw;
            mx.x = fmaxf(mx.x, vx); mx.y = fmaxf(mx.y, vy);
            mx.z = fmaxf(mx.z, vz); mx.w = fmaxf(mx.w, vw);
        }
#pragma unroll
        for (int o = 16; o; o >>= 1) {
            mx.x = fmaxf(mx.x, __shfl_xor_sync(0xffffffffu, mx.x, o));
            mx.y = fmaxf(mx.y, __shfl_xor_sync(0xffffffffu, mx.y, o));
            mx.z = fmaxf(mx.z, __shfl_xor_sync(0xffffffffu, mx.z, o));
            mx.w = fmaxf(mx.w, __shfl_xor_sync(0xffffffffu, mx.w, o));
        }

        int head = lane >> 3;
        float4 zs = make_float4(0.f, 0.f, 0.f, 0.f);
        int i = start;
        for (; i + 3 < end; i += 4) {
            int s0 = sp[i], s1 = sp[i + 1], s2 = sp[i + 2], s3 = sp[i + 3];
            float4 f0 = *(const float4*)&fp[(size_t)s0 * 128 + lane * 4];
            float4 f1 = *(const float4*)&fp[(size_t)s1 * 128 + lane * 4];
            float4 f2 = *(const float4*)&fp[(size_t)s2 * 128 + lane * 4];
            float4 f3 = *(const float4*)&fp[(size_t)s3 * 128 + lane * 4];
            float4 a0 = elp[s0], a1 = elp[s1], a2 = elp[s2], a3 = elp[s3];
            float4 w0 = edge_w(a0, er4, mx), w1 = edge_w(a1, er4, mx);
            float4 w2 = edge_w(a2, er4, mx), w3 = edge_w(a3, er4, mx);
            zs.x += (w0.x + w1.x) + (w2.x + w3.x);
            zs.y += (w0.y + w1.y) + (w2.y + w3.y);
            zs.z += (w0.z + w1.z) + (w2.z + w3.z);
            zs.w += (w0.w + w1.w) + (w2.w + w3.w);
            float c0 = head == 0 ? w0.x : head == 1 ? w0.y : head == 2 ? w0.z : w0.w;
            float c1 = head == 0 ? w1.x : head == 1 ? w1.y : head == 2 ? w1.z : w1.w;
            float c2 = head == 0 ? w2.x : head == 1 ? w2.y : head == 2 ? w2.z : w2.w;
            float c3 = head == 0 ? w3.x : head == 1 ? w3.y : head == 2 ? w3.z : w3.w;
            acc.x = fmaf(c0, f0.x, acc.x); acc.x = fmaf(c1, f1.x, acc.x);
            acc.x = fmaf(c2, f2.x, acc.x); acc.x = fmaf(c3, f3.x, acc.x);
            acc.y = fmaf(c0, f0.y, acc.y); acc.y = fmaf(c1, f1.y, acc.y);
            acc.y = fmaf(c2, f2.y, acc.y); acc.y = fmaf(c3, f3.y, acc.y);
            acc.z = fmaf(c0, f0.z, acc.z); acc.z = fmaf(c1, f1.z, acc.z);
            acc.z = fmaf(c2, f2.z, acc.z); acc.z = fmaf(c3, f3.z, acc.z);
            acc.w = fmaf(c0, f0.w, acc.w); acc.w = fmaf(c1, f1.w, acc.w);
            acc.w = fmaf(c2, f2.w, acc.w); acc.w = fmaf(c3, f3.w, acc.w);
        }
        for (; i < end; i++) {
            int s0 = sp[i];
            float4 f0 = *(const float4*)&fp[(size_t)s0 * 128 + lane * 4];
            float4 w0 = edge_w(elp[s0], er4, mx);
            zs.x += w0.x; zs.y += w0.y; zs.z += w0.z; zs.w += w0.w;
            float c0 = head == 0 ? w0.x : head == 1 ? w0.y : head == 2 ? w0.z : w0.w;
            acc.x = fmaf(c0, f0.x, acc.x);
            acc.y = fmaf(c0, f0.y, acc.y);
            acc.z = fmaf(c0, f0.z, acc.z);
            acc.w = fmaf(c0, f0.w, acc.w);
        }
        float zsel = head == 0 ? zs.x : head == 1 ? zs.y : head == 2 ? zs.z : zs.w;
        float inv = 1.f / zsel;
        acc.x *= inv; acc.y *= inv; acc.z *= inv; acc.w *= inv;
        acc.x = acc.x > 0.f ? acc.x : expm1f(acc.x);
        acc.y = acc.y > 0.f ? acc.y : expm1f(acc.y);
        acc.z = acc.z > 0.f ? acc.z : expm1f(acc.z);
        acc.w = acc.w > 0.f ? acc.w : expm1f(acc.w);
    }
    __nv_bfloat16 hv[4], lv[4];
#pragma unroll
    for (int q = 0; q < 4; q++) {
        float v = (&acc.x)[q];
        __nv_bfloat16 hh = __float2bfloat16(v);
        hv[q] = hh;
        lv[q] = __float2bfloat16(v - __bfloat162float(hh));
    }
    *(uint2*)&zh[(size_t)r * 128 + lane * 4] = *(uint2*)hv;
    *(uint2*)&zl[(size_t)r * 128 + lane * 4] = *(uint2*)lv;
}

// ---------------- softmax over meta-paths + combine -----------------------------------
__global__ void k_bsem(const float* __restrict__ wsem, float* __restrict__ bsem) {
    float w0 = wsem[0] / (float)Nn, w1 = wsem[1] / (float)Nn, w2 = wsem[2] / (float)Nn;
    float m = fmaxf(w0, fmaxf(w1, w2));
    float e0 = expf(w0 - m), e1 = expf(w1 - m), e2 = expf(w2 - m);
    float s = e0 + e1 + e2;
    bsem[0] = e0 / s; bsem[1] = e1 / s; bsem[2] = e2 / s;
}

__global__ void k_comb(const __nv_bfloat16* __restrict__ zh, const __nv_bfloat16* __restrict__ zl,
                       const float* __restrict__ bsem, float* __restrict__ out) {
    long i = (long)blockIdx.x * 256 + threadIdx.x;
    if (i >= (long)Nn * 32) return;
    float b[3] = {bsem[0], bsem[1], bsem[2]};
    float4 o = make_float4(0.f, 0.f, 0.f, 0.f);
#pragma unroll
    for (int p = 0; p < 3; p++) {
        size_t base = (size_t)p * Nn * 128 + i * 4;
        uint2 uh = *(const uint2*)&zh[base];
        uint2 ul = *(const uint2*)&zl[base];
        float2 h0 = __bfloat1622float2(*(__nv_bfloat162*)&uh.x);
        float2 h1 = __bfloat1622float2(*(__nv_bfloat162*)&uh.y);
        float2 l0 = __bfloat1622float2(*(__nv_bfloat162*)&ul.x);
        float2 l1 = __bfloat1622float2(*(__nv_bfloat162*)&ul.y);
        o.x = fmaf(b[p], h0.x + l0.x, o.x);
        o.y = fmaf(b[p], h0.y + l0.y, o.y);
        o.z = fmaf(b[p], h1.x + l1.x, o.z);
        o.w = fmaf(b[p], h1.y + l1.y, o.w);
    }
    ((float4*)out)[i] = o;
}

// ---------------- launch: two-stream fork/join overlap ---------------------------------
extern "C" void kernel_launch(void* const* d_in, const int* in_sizes, int n_in,
                              void* d_out, int out_size) {
    const float* h      = (const float*)d_in[0];
    const float* cf     = (const float*)d_in[1];
    const float* fa_w1  = (const float*)d_in[2];
    const float* fa_b1  = (const float*)d_in[3];
    const float* fa_w2  = (const float*)d_in[4];
    const float* gat_W  = (const float*)d_in[5];
    const float* attn_l = (const float*)d_in[6];
    const float* attn_r = (const float*)d_in[7];
    const float* sa_w1  = (const float*)d_in[8];
    const float* sa_b1  = (const float*)d_in[9];
    const float* sa_w2  = (const float*)d_in[10];
    const int*   src    = (const int*)d_in[11];
    const int*   dst    = (const int*)d_in[12];
    float* out = (float*)d_out;

    float *pfeat, *pel, *per, *pwsem, *pbsem;
    int *pdeg, *poff, *pcur, *pcsrc;
    __nv_bfloat16 *pbh, *pbl, *pxh, *pxl, *pzh, *pzl;
    cudaGetSymbolAddress((void**)&pxh, g_x_hi);
    cudaGetSymbolAddress((void**)&pxl, g_x_lo);
    cudaGetSymbolAddress((void**)&pfeat, g_feat);
    cudaGetSymbolAddress((void**)&pzh, g_z_hi);
    cudaGetSymbolAddress((void**)&pzl, g_z_lo);
    cudaGetSymbolAddress((void**)&pel, g_el);
    cudaGetSymbolAddress((void**)&per, g_er);
    cudaGetSymbolAddress((void**)&pdeg, g_deg);
    cudaGetSymbolAddress((void**)&poff, g_off);
    cudaGetSymbolAddress((void**)&pcur, g_cur);
    cudaGetSymbolAddress((void**)&pcsrc, g_csrc);
    cudaGetSymbolAddress((void**)&pbh, g_bt_hi);
    cudaGetSymbolAddress((void**)&pbl, g_bt_lo);
    cudaGetSymbolAddress((void**)&pwsem, g_wsem);
    cudaGetSymbolAddress((void**)&pbsem, g_bsem);

    cudaFuncSetAttribute(k_gemm_feat, cudaFuncAttributeMaxDynamicSharedMemorySize, SMEM_TOT);
    cudaFuncSetAttribute(k_semgemm, cudaFuncAttributeMaxDynamicSharedMemorySize, SMEM_TOT);

    // fork a non-blocking side stream off the captured (default) stream
    cudaStream_t s2;
    cudaEvent_t evFork, evJoin;
    cudaStreamCreateWithFlags(&s2, cudaStreamNonBlocking);
    cudaEventCreateWithFlags(&evFork, cudaEventDisableTiming);
    cudaEventCreateWithFlags(&evJoin, cudaEventDisableTiming);

    cudaEventRecord(evFork, 0);
    cudaStreamWaitEvent(s2, evFork, 0);

    // side stream: CSR build chain (independent of x-chain until k_gather)
    dim3 ge4((Ee + 1023) / 1024, Pp);
    cudaMemsetAsync(pdeg, 0, sizeof(int) * (size_t)Pp * Nn, s2);
    k_count<<<ge4, 256, 0, s2>>>(dst, pdeg);
    k_scan<<<Pp, 1024, 0, s2>>>(pdeg, poff, pcur);
    k_scatter<<<ge4, 256, 0, s2>>>(src, dst, pcur, pcsrc);
    cudaEventRecord(evJoin, s2);

    // main stream: x-chain
    cudaMemsetAsync(pwsem, 0, sizeof(float) * Pp, 0);
    k_wprep<<<(4 * 16384 + 255) / 256, 256>>>(gat_W, sa_w1, pbh, pbl);
    k_featatt<<<(Nn + 7) / 8, 256>>>(h, cf, fa_w1, fa_b1, fa_w2, pxh, pxl);
    dim3 gg((Nn + 127) / 128, Pp);
    k_gemm_feat<<<gg, 256, SMEM_TOT>>>(pxh, pxl, pbh, pbl, attn_l, attn_r, pfeat, pel, per);

    // join, then edge aggregation + semantic attention
    cudaStreamWaitEvent(0, evJoin, 0);
    dim3 gn((Nn + 7) / 8, Pp);
    k_gather<<<gn, 256>>>(pcsrc, poff, pel, per, pfeat, pzh, pzl);

    k_semgemm<<<gg, 256, SMEM_TOT>>>(pzh, pzl, pbh + 3 * 16384, pbl + 3 * 16384, sa_b1, sa_w2, pwsem);
    k_bsem<<<1, 1>>>(pwsem, pbsem);
    k_comb<<<(unsigned)(((long)Nn * 32 + 255) / 256), 256>>>(pzh, pzl, pbsem, out);

    cudaStreamDestroy(s2);
    cudaEventDestroy(evFork);
    cudaEventDestroy(evJoin);
}

// round 12
// speedup vs baseline: 1.0340x; 1.0340x over previous
#include <cuda_runtime.h>
#include <cuda_bf16.h>
#include <cuda_fp16.h>
#include <math.h>
#include <stdint.h>

#define Nn 50000
#define Ee 400000
#define Pp 3

// ---------------- scratch (device globals) --------------------------------------
__device__ __align__(16) __nv_bfloat16 g_x_hi[(size_t)Nn * 128];
__device__ __align__(16) __nv_bfloat16 g_x_lo[(size_t)Nn * 128];
__device__ __align__(16) __half g_feat[(size_t)Pp * Nn * 128];   // fp16 feat
__device__ __align__(16) __nv_bfloat16 g_z_hi[(size_t)Pp * Nn * 128];
__device__ __align__(16) __nv_bfloat16 g_z_lo[(size_t)Pp * Nn * 128];
__device__ __align__(16) float g_el[(size_t)Pp * Nn * 4];
__device__ __align__(16) float g_er[(size_t)Pp * Nn * 4];
__device__ int g_deg[(size_t)Pp * Nn];
__device__ int g_off[(size_t)Pp * (Nn + 1)];
__device__ int g_cur[(size_t)Pp * Nn];
__device__ int g_csrc[(size_t)Pp * Ee];
__device__ __align__(16) __nv_bfloat16 g_bt_hi[4 * 128 * 128];
__device__ __align__(16) __nv_bfloat16 g_bt_lo[4 * 128 * 128];
__device__ float g_wsem[Pp];
__device__ float g_bsem[Pp];

// ---------------- smem layout ------------------------------------------------------
#define SROW 72
#define TILEB (128 * SROW * 2)
#define S_AUX0 0
#define S_AUX1 512
#define S_RED  1024
#define S_A0H  2048
#define S_A0L  (S_A0H + TILEB)
#define S_A1H  (S_A0L + TILEB)
#define S_A1L  (S_A1H + TILEB)
#define S_BH   (S_A1L + TILEB)
#define S_BL   (S_BH + TILEB)
#define SMEM_TOT (S_BL + TILEB)       // 112640
#define SDW 132

__device__ __forceinline__ void mma16816(float& d0, float& d1, float& d2, float& d3,
                                         uint32_t a0, uint32_t a1, uint32_t a2, uint32_t a3,
                                         uint32_t b0, uint32_t b1) {
    asm volatile(
        "mma.sync.aligned.m16n8k16.row.col.f32.bf16.bf16.f32 "
        "{%0,%1,%2,%3}, {%4,%5,%6,%7}, {%8,%9}, {%0,%1,%2,%3};"
        : "+f"(d0), "+f"(d1), "+f"(d2), "+f"(d3)
        : "r"(a0), "r"(a1), "r"(a2), "r"(a3), "r"(b0), "r"(b1));
}

__device__ __forceinline__ void ldsm4(uint32_t& r0, uint32_t& r1, uint32_t& r2,
                                      uint32_t& r3, uint32_t addr) {
    asm volatile("ldmatrix.sync.aligned.m8n8.x4.shared.b16 {%0,%1,%2,%3}, [%4];"
                 : "=r"(r0), "=r"(r1), "=r"(r2), "=r"(r3) : "r"(addr));
}

__device__ __forceinline__ void cpa16(uint32_t dst, const void* src, int sz) {
    asm volatile("cp.async.cg.shared.global [%0], [%1], 16, %2;"
                 :: "r"(dst), "l"(src), "r"(sz));
}
#define CP_COMMIT() asm volatile("cp.async.commit_group;" ::: "memory")
#define CP_WAIT(n)  asm volatile("cp.async.wait_group %0;" :: "n"(n) : "memory")

template <bool FULL>
__device__ __forceinline__ void fill_A(uint32_t sbase, const __nv_bfloat16* ah,
                                       const __nv_bfloat16* al, int n0, int slab, int tid) {
    const int ITS = FULL ? 8 : 4;
#pragma unroll
    for (int it = 0; it < ITS; it++) {
        int idx = it * 256 + tid;
        int prec = idx >> 10;
        int rem = idx & 1023;
        int row = rem >> 3;
        int ch = rem & 7;
        int n = n0 + row;
        int nc = n < Nn ? n : Nn - 1;
        const __nv_bfloat16* s = (prec ? al : ah) + (size_t)nc * 128 + slab * 64 + ch * 8;
        uint32_t d = sbase + (uint32_t)(prec * TILEB + (row * SROW + ch * 8) * 2);
        cpa16(d, s, n < Nn ? 16 : 0);
    }
}

__device__ __forceinline__ void fill_B(uint32_t sbase, const __nv_bfloat16* bh,
                                       const __nv_bfloat16* bl, int slab, int tid) {
#pragma unroll
    for (int it = 0; it < 8; it++) {
        int idx = it * 256 + tid;
        int prec = idx >> 10;
        int rem = idx & 1023;
        int row = rem >> 3;
        int ch = rem & 7;
        const __nv_bfloat16* s = (prec ? bl : bh) + (size_t)row * 128 + slab * 64 + ch * 8;
        uint32_t d = sbase + (uint32_t)(prec * TILEB + (row * SROW + ch * 8) * 2);
        cpa16(d, s, 16);
    }
}

template <bool FULL>
__device__ __forceinline__ void mma_slab(uint32_t smem_s, uint32_t abase, float d[2][8][4],
                                         int lane, int wid) {
    int warpM = wid & 3, warpN = wid >> 2;
    int grp = lane >> 3, lr = lane & 7;
    uint32_t aA = smem_s + abase +
        (uint32_t)(((warpM * 32 + lr + (grp & 1) * 8) * SROW + (grp >> 1) * 8) * 2);
    uint32_t aB = smem_s + S_BH +
        (uint32_t)(((warpN * 64 + lr + (grp >> 1) * 8) * SROW + (grp & 1) * 8) * 2);
    const uint32_t MT = 16 * SROW * 2;

#pragma unroll
    for (int ks = 0; ks < 4; ks++) {
        uint32_t kb = (uint32_t)(ks * 32);
        uint32_t ah[2][4], al[2][4], bb[4][4];
#pragma unroll
        for (int mt = 0; mt < 2; mt++) {
            ldsm4(ah[mt][0], ah[mt][1], ah[mt][2], ah[mt][3], aA + mt * MT + kb);
            if (FULL)
                ldsm4(al[mt][0], al[mt][1], al[mt][2], al[mt][3], aA + TILEB + mt * MT + kb);
        }
#pragma unroll
        for (int np = 0; np < 4; np++)
            ldsm4(bb[np][0], bb[np][1], bb[np][2], bb[np][3], aB + np * MT + kb);
#pragma unroll
        for (int np = 0; np < 4; np++)
#pragma unroll
            for (int mt = 0; mt < 2; mt++) {
                mma16816(d[mt][2 * np][0], d[mt][2 * np][1], d[mt][2 * np][2], d[mt][2 * np][3],
                         ah[mt][0], ah[mt][1], ah[mt][2], ah[mt][3], bb[np][0], bb[np][1]);
                mma16816(d[mt][2 * np + 1][0], d[mt][2 * np + 1][1], d[mt][2 * np + 1][2], d[mt][2 * np + 1][3],
                         ah[mt][0], ah[mt][1], ah[mt][2], ah[mt][3], bb[np][2], bb[np][3]);
            }
        if (FULL) {
#pragma unroll
            for (int np = 0; np < 4; np++)
#pragma unroll
                for (int mt = 0; mt < 2; mt++) {
                    mma16816(d[mt][2 * np][0], d[mt][2 * np][1], d[mt][2 * np][2], d[mt][2 * np][3],
                             al[mt][0], al[mt][1], al[mt][2], al[mt][3], bb[np][0], bb[np][1]);
                    mma16816(d[mt][2 * np + 1][0], d[mt][2 * np + 1][1], d[mt][2 * np + 1][2], d[mt][2 * np + 1][3],
                             al[mt][0], al[mt][1], al[mt][2], al[mt][3], bb[np][2], bb[np][3]);
                }
        }
#pragma unroll
        for (int np = 0; np < 4; np++)
            ldsm4(bb[np][0], bb[np][1], bb[np][2], bb[np][3], aB + TILEB + np * MT + kb);
#pragma unroll
        for (int np = 0; np < 4; np++)
#pragma unroll
            for (int mt = 0; mt < 2; mt++) {
                mma16816(d[mt][2 * np][0], d[mt][2 * np][1], d[mt][2 * np][2], d[mt][2 * np][3],
                         ah[mt][0], ah[mt][1], ah[mt][2], ah[mt][3], bb[np][0], bb[np][1]);
                mma16816(d[mt][2 * np + 1][0], d[mt][2 * np + 1][1], d[mt][2 * np + 1][2], d[mt][2 * np + 1][3],
                         ah[mt][0], ah[mt][1], ah[mt][2], ah[mt][3], bb[np][2], bb[np][3]);
            }
    }
}

template <bool FULL>
__device__ __forceinline__ void gemm_core(const __nv_bfloat16* __restrict__ ah,
                                          const __nv_bfloat16* __restrict__ alo,
                                          int n0,
                                          const __nv_bfloat16* __restrict__ bth,
                                          const __nv_bfloat16* __restrict__ btl,
                                          char* smem, float d[2][8][4]) {
    int tid = threadIdx.x, lane = tid & 31, wid = tid >> 5;
    uint32_t smem_s = (uint32_t)__cvta_generic_to_shared(smem);

    fill_B(smem_s + S_BH, bth, btl, 0, tid);
    fill_A<FULL>(smem_s + S_A0H, ah, alo, n0, 0, tid);
    CP_COMMIT();
    fill_A<FULL>(smem_s + S_A1H, ah, alo, n0, 1, tid);
    CP_COMMIT();
    CP_WAIT(1);
    __syncthreads();
    mma_slab<FULL>(smem_s, S_A0H, d, lane, wid);
    __syncthreads();
    fill_B(smem_s + S_BH, bth, btl, 1, tid);
    CP_COMMIT();
    CP_WAIT(0);
    __syncthreads();
    mma_slab<FULL>(smem_s, S_A1H, d, lane, wid);
    __syncthreads();
}

__device__ __forceinline__ void stage_d(float* sd, float d[2][8][4], int lane, int wid) {
    int warpM = wid & 3, warpN = wid >> 2;
    int rq = lane >> 2, cq = (lane & 3) * 2;
#pragma unroll
    for (int mt = 0; mt < 2; mt++) {
        int rl0 = warpM * 32 + mt * 16 + rq;
        int rl1 = rl0 + 8;
#pragma unroll
        for (int nt = 0; nt < 8; nt++) {
            int c = warpN * 64 + nt * 8 + cq;
            *(float2*)&sd[rl0 * SDW + c] = make_float2(d[mt][nt][0], d[mt][nt][1]);
            *(float2*)&sd[rl1 * SDW + c] = make_float2(d[mt][nt][2], d[mt][nt][3]);
        }
    }
}

// ---------------- projection GEMM + fused el/er (fp16 feat out) ---------------------
__global__ void __launch_bounds__(256, 2) k_gemm_feat(
    const __nv_bfloat16* __restrict__ xh, const __nv_bfloat16* __restrict__ xl,
    const __nv_bfloat16* __restrict__ bth, const __nv_bfloat16* __restrict__ btl,
    const float* __restrict__ al, const float* __restrict__ ar,
    __half* __restrict__ feat, float* __restrict__ el, float* __restrict__ er) {
    extern __shared__ char smem[];
    int tid = threadIdx.x, lane = tid & 31, wid = tid >> 5;
    int p = blockIdx.y;
    int n0 = blockIdx.x * 128;
    float* sal = (float*)(smem + S_AUX0);
    float* sar = (float*)(smem + S_AUX1);
    if (tid < 128) { sal[tid] = al[p * 128 + tid]; sar[tid] = ar[p * 128 + tid]; }

    float d[2][8][4];
#pragma unroll
    for (int mt = 0; mt < 2; mt++)
#pragma unroll
        for (int nt = 0; nt < 8; nt++)
#pragma unroll
            for (int q = 0; q < 4; q++) d[mt][nt][q] = 0.f;

    gemm_core<true>(xh, xl, n0, bth + (size_t)p * 16384, btl + (size_t)p * 16384, smem, d);

    float* sd = (float*)(smem + S_A0H);
    stage_d(sd, d, lane, wid);
    __syncthreads();

    int row = tid >> 1, half = tid & 1;
    int n = n0 + row;
    if (n < Nn) {
        float sel[2] = {0.f, 0.f}, ser[2] = {0.f, 0.f};
        __half* o = &feat[((size_t)p * Nn + n) * 128 + half * 64];
#pragma unroll
        for (int q = 0; q < 16; q++) {
            float4 v = *(float4*)&sd[row * SDW + half * 64 + q * 4];
            __half2 h0 = __floats2half2_rn(v.x, v.y);
            __half2 h1 = __floats2half2_rn(v.z, v.w);
            *(uint2*)&o[q * 4] = make_uint2(*(uint32_t*)&h0, *(uint32_t*)&h1);
            int hb = q >> 3;
            int c = half * 64 + q * 4;
            sel[hb] = fmaf(v.x, sal[c + 0], sel[hb]);
            sel[hb] = fmaf(v.y, sal[c + 1], sel[hb]);
            sel[hb] = fmaf(v.z, sal[c + 2], sel[hb]);
            sel[hb] = fmaf(v.w, sal[c + 3], sel[hb]);
            ser[hb] = fmaf(v.x, sar[c + 0], ser[hb]);
            ser[hb] = fmaf(v.y, sar[c + 1], ser[hb]);
            ser[hb] = fmaf(v.z, sar[c + 2], ser[hb]);
            ser[hb] = fmaf(v.w, sar[c + 3], ser[hb]);
        }
        *(float2*)&el[((size_t)p * Nn + n) * 4 + half * 2] = make_float2(sel[0], sel[1]);
        *(float2*)&er[((size_t)p * Nn + n) * 4 + half * 2] = make_float2(ser[0], ser[1]);
    }
}

// ---------------- semantic GEMM (2-pass) + tanh/w2 reduce ---------------------------
__global__ void __launch_bounds__(256, 2) k_semgemm(
    const __nv_bfloat16* __restrict__ zh, const __nv_bfloat16* __restrict__ zl,
    const __nv_bfloat16* __restrict__ bth, const __nv_bfloat16* __restrict__ btl,
    const float* __restrict__ b1, const float* __restrict__ w2, float* __restrict__ wsem) {
    extern __shared__ char smem[];
    int tid = threadIdx.x, lane = tid & 31, wid = tid >> 5;
    int p = blockIdx.y;
    int n0 = blockIdx.x * 128;
    float* sb1 = (float*)(smem + S_AUX0);
    float* sw2 = (float*)(smem + S_AUX1);
    float* sred = (float*)(smem + S_RED);
    if (tid < 128) { sb1[tid] = b1[tid]; sw2[tid] = w2[tid]; }

    float d[2][8][4];
#pragma unroll
    for (int mt = 0; mt < 2; mt++)
#pragma unroll
        for (int nt = 0; nt < 8; nt++)
#pragma unroll
            for (int q = 0; q < 4; q++) d[mt][nt][q] = 0.f;

    gemm_core<false>(zh + (size_t)p * Nn * 128, zl, n0, bth, btl, smem, d);

    float* sd = (float*)(smem + S_A0H);
    stage_d(sd, d, lane, wid);
    __syncthreads();

    int row = tid >> 1, half = tid & 1;
    int n = n0 + row;
    float accv = 0.f;
    if (n < Nn) {
#pragma unroll
        for (int q = 0; q < 16; q++) {
            float4 v = *(float4*)&sd[row * SDW + half * 64 + q * 4];
            int c = half * 64 + q * 4;
            accv = fmaf(tanhf(v.x + sb1[c + 0]), sw2[c + 0], accv);
            accv = fmaf(tanhf(v.y + sb1[c + 1]), sw2[c + 1], accv);
            accv = fmaf(tanhf(v.z + sb1[c + 2]), sw2[c + 2], accv);
            accv = fmaf(tanhf(v.w + sb1[c + 3]), sw2[c + 3], accv);
        }
    }
#pragma unroll
    for (int o = 16; o; o >>= 1) accv += __shfl_xor_sync(0xffffffffu, accv, o);
    if (lane == 0) sred[wid] = accv;
    __syncthreads();
    if (tid == 0) {
        float s = 0.f;
#pragma unroll
        for (int i = 0; i < 8; i++) s += sred[i];
        atomicAdd(&wsem[p], s);
    }
}

// ---------------- feature attention: warp per node ----------------------------------
__global__ void k_featatt(const float* __restrict__ h, const float* __restrict__ cf,
                          const float* __restrict__ w1, const float* __restrict__ b1,
                          const float* __restrict__ w2,
                          __nv_bfloat16* __restrict__ xh, __nv_bfloat16* __restrict__ xl) {
    __shared__ float sw1[42 * 16];
    __shared__ float sb1[16], sw2[16];
    __shared__ __align__(16) float sf[8][840];
    __shared__ float ss[8][20];
    int tid = threadIdx.x, wid = tid >> 5, lane = tid & 31;
    for (int i = tid; i < 672; i += 256) sw1[i] = w1[i];
    if (tid < 16) { sb1[tid] = b1[tid]; sw2[tid] = w2[tid]; }
    __syncthreads();
    int n = blockIdx.x * 8 + wid;
    if (n >= Nn) return;

    const float4* fr4 = (const float4*)(cf + (size_t)n * 840);
    float* myf = sf[wid];
    float4* myf4 = (float4*)myf;
    for (int i = lane; i < 210; i += 32) myf4[i] = fr4[i];
    __syncwarp();

    int k = lane & 15;
    for (int j0 = 0; j0 < 20; j0 += 2) {
        int j = j0 + (lane >> 4);
        const float* fj = myf + j * 42;
        float acc = sb1[k];
#pragma unroll
        for (int i = 0; i < 42; i++) acc = fmaf(fj[i], sw1[i * 16 + k], acc);
        float v = tanhf(acc) * sw2[k];
#pragma unroll
        for (int off = 8; off; off >>= 1) v += __shfl_down_sync(0xffffffffu, v, off);
        if (k == 0) ss[wid][j] = v;
    }
    __syncwarp();

    float sc = (lane < 20) ? ss[wid][lane] : -INFINITY;
    float mx = sc;
#pragma unroll
    for (int off = 16; off; off >>= 1) mx = fmaxf(mx, __shfl_xor_sync(0xffffffffu, mx, off));
    float ex = (lane < 20) ? expf(sc - mx) : 0.f;
    float sm = ex;
#pragma unroll
    for (int off = 16; off; off >>= 1) sm += __shfl_xor_sync(0xffffffffu, sm, off);
    float beta = ex / sm;

    float a0 = 0.f, a1 = 0.f;
    for (int j = 0; j < 20; j++) {
        float bj = __shfl_sync(0xffffffffu, beta, j);
        a0 = fmaf(bj, myf[j * 42 + lane], a0);
        if (lane < 10) a1 = fmaf(bj, myf[j * 42 + 32 + lane], a1);
    }
    const float* hr = h + (size_t)n * 86;
    __nv_bfloat16* xhr = xh + (size_t)n * 128;
    __nv_bfloat16* xlr = xl + (size_t)n * 128;
    for (int i = lane; i < 86; i += 32) {
        float v = hr[i];
        __nv_bfloat16 hh = __float2bfloat16(v);
        xhr[i] = hh;
        xlr[i] = __float2bfloat16(v - __bfloat162float(hh));
    }
    {
        __nv_bfloat16 hh = __float2bfloat16(a0);
        xhr[86 + lane] = hh;
        xlr[86 + lane] = __float2bfloat16(a0 - __bfloat162float(hh));
    }
    if (lane < 10) {
        __nv_bfloat16 hh = __float2bfloat16(a1);
        xhr[118 + lane] = hh;
        xlr[118 + lane] = __float2bfloat16(a1 - __bfloat162float(hh));
    }
}

// ---------------- weight prep ---------------------------------------------------------
__global__ void k_wprep(const float* __restrict__ gatW, const float* __restrict__ saw1,
                        __nv_bfloat16* __restrict__ bh, __nv_bfloat16* __restrict__ bl) {
    int idx = blockIdx.x * 256 + threadIdx.x;
    if (idx >= 4 * 16384) return;
    int slot = idx >> 14, rem = idx & 16383;
    int nIdx = rem >> 7, kIdx = rem & 127;
    float v = (slot < 3) ? gatW[slot * 16384 + kIdx * 128 + nIdx] : saw1[kIdx * 128 + nIdx];
    __nv_bfloat16 hh = __float2bfloat16(v);
    bh[idx] = hh;
    bl[idx] = __float2bfloat16(v - __bfloat162float(hh));
}

// ---------------- CSR build (4-way ILP atomics) ----------------------------------------
__global__ void k_count(const int* __restrict__ dst, int* __restrict__ deg) {
    int p = blockIdx.y;
    int base = blockIdx.x * 1024 + threadIdx.x;
#pragma unroll
    for (int j = 0; j < 4; j++) {
        int e = base + j * 256;
        if (e < Ee) atomicAdd(&deg[(size_t)p * Nn + dst[(size_t)p * Ee + e]], 1);
    }
}

__global__ void k_scan(const int* __restrict__ deg, int* __restrict__ off,
                       int* __restrict__ cur) {
    int p = blockIdx.x;
    int tid = threadIdx.x, lane = tid & 31, wid = tid >> 5;
    __shared__ int wsum[32];
    __shared__ int carry;
    if (tid == 0) carry = 0;
    __syncthreads();
    for (int base = 0; base < Nn; base += 1024) {
        int i = base + tid;
        int v = (i < Nn) ? deg[(size_t)p * Nn + i] : 0;
        int xv = v;
#pragma unroll
        for (int o = 1; o < 32; o <<= 1) {
            int t = __shfl_up_sync(0xffffffffu, xv, o);
            if (lane >= o) xv += t;
        }
        if (lane == 31) wsum[wid] = xv;
        __syncthreads();
        if (wid == 0) {
            int y = wsum[lane];
#pragma unroll
            for (int o = 1; o < 32; o <<= 1) {
                int t = __shfl_up_sync(0xffffffffu, y, o);
                if (lane >= o) y += t;
            }
            wsum[lane] = y;
        }
        __syncthreads();
        int wpre = (wid == 0) ? 0 : wsum[wid - 1];
        int excl = carry + wpre + xv - v;
        if (i < Nn) {
            off[(size_t)p * (Nn + 1) + i] = excl;
            cur[(size_t)p * Nn + i] = excl;
        }
        __syncthreads();
        if (tid == 1023) carry = excl + v;
        __syncthreads();
    }
    if (tid == 0) off[(size_t)p * (Nn + 1) + Nn] = carry;
}

__global__ void k_scatter(const int* __restrict__ src, const int* __restrict__ dst,
                          int* __restrict__ cur, int* __restrict__ csrc) {
    int p = blockIdx.y;
    int base = blockIdx.x * 1024 + threadIdx.x;
    int ev[4], dv[4], sv[4];
#pragma unroll
    for (int j = 0; j < 4; j++) {
        ev[j] = base + j * 256;
        if (ev[j] < Ee) {
            dv[j] = dst[(size_t)p * Ee + ev[j]];
            sv[j] = src[(size_t)p * Ee + ev[j]];
        }
    }
#pragma unroll
    for (int j = 0; j < 4; j++) {
        if (ev[j] < Ee) {
            int pos = atomicAdd(&cur[(size_t)p * Nn + dv[j]], 1);
            csrc[(size_t)p * Ee + pos] = sv[j];
        }
    }
}

// ---------------- gather aggregation: warp per (p, dst), fp16 feat --------------------
__global__ void k_gather(const int* __restrict__ csrc, const int* __restrict__ off,
                         const float* __restrict__ el, const float* __restrict__ er,
                         const __half* __restrict__ feat,
                         __nv_bfloat16* __restrict__ zh, __nv_bfloat16* __restrict__ zl) {
    int p = blockIdx.y;
    int tid = threadIdx.x, wid = tid >> 5, lane = tid & 31;
    int n = blockIdx.x * 8 + wid;
    if (n >= Nn) return;
    long r = (long)p * Nn + n;
    int start = off[(size_t)p * (Nn + 1) + n];
    int end = off[(size_t)p * (Nn + 1) + n + 1];
    float4 acc = make_float4(0.f, 0.f, 0.f, 0.f);
    if (start < end) {
        const int* sp = csrc + (size_t)p * Ee;
        const float4* elp = (const float4*)el + (size_t)p * Nn;
        const __half* fp = feat + (size_t)p * Nn * 128;
        float4 er4 = ((const float4*)er)[r];

        float4 mx = make_float4(-INFINITY, -INFINITY, -INFINITY, -INFINITY);
        for (int i = start + lane; i < end; i += 32) {
            float4 a = elp[sp[i]];
            float vx = a.x + er4.x; vx = vx > 0.f ? vx : 0.2f * vx;
            float vy = a.y + er4.y; vy = vy > 0.f ? vy : 0.2f * vy;
            float vz = a.z + er4.z; vz = vz > 0.f ? vz : 0.2f * vz;
            float vw = a.w + er4.w; vw = vw > 0.f ? vw : 0.2f * vw;
            mx.x = fmaxf(mx.x, vx); mx.y = fmaxf(mx.y, vy);
            mx.z = fmaxf(mx.z, vz); mx.w = fmaxf(mx.w, vw);
        }
#pragma unroll
        for (int o = 16; o; o >>= 1) {
            mx.x = fmaxf(mx.x, __shfl_xor_sync(0xffffffffu, mx.x, o));
            mx.y = fmaxf(mx.y, __shfl_xor_sync(0xffffffffu, mx.y, o));
            mx.z = fmaxf(mx.z, __shfl_xor_sync(0xffffffffu, mx.z, o));
            mx.w = fmaxf(mx.w, __shfl_xor_sync(0xffffffffu, mx.w, o));
        }

        int head = lane >> 3;
        float4 zs = make_float4(0.f, 0.f, 0.f, 0.f);
        int i = start;
        for (; i + 1 < end; i += 2) {
            int s0 = sp[i], s1 = sp[i + 1];
            float4 a0 = elp[s0], a1 = elp[s1];
            uint2 u0 = *(const uint2*)&fp[(size_t)s0 * 128 + lane * 4];
            uint2 u1 = *(const uint2*)&fp[(size_t)s1 * 128 + lane * 4];
            float2 f0a = __half22float2(*(__half2*)&u0.x);
            float2 f0b = __half22float2(*(__half2*)&u0.y);
            float2 f1a = __half22float2(*(__half2*)&u1.x);
            float2 f1b = __half22float2(*(__half2*)&u1.y);
            float4 w0, w1;
            float t;
            t = a0.x + er4.x; t = t > 0.f ? t : 0.2f * t; w0.x = __expf(t - mx.x);
            t = a0.y + er4.y; t = t > 0.f ? t : 0.2f * t; w0.y = __expf(t - mx.y);
            t = a0.z + er4.z; t = t > 0.f ? t : 0.2f * t; w0.z = __expf(t - mx.z);
            t = a0.w + er4.w; t = t > 0.f ? t : 0.2f * t; w0.w = __expf(t - mx.w);
            t = a1.x + er4.x; t = t > 0.f ? t : 0.2f * t; w1.x = __expf(t - mx.x);
            t = a1.y + er4.y; t = t > 0.f ? t : 0.2f * t; w1.y = __expf(t - mx.y);
            t = a1.z + er4.z; t = t > 0.f ? t : 0.2f * t; w1.z = __expf(t - mx.z);
            t = a1.w + er4.w; t = t > 0.f ? t : 0.2f * t; w1.w = __expf(t - mx.w);
            zs.x += w0.x + w1.x; zs.y += w0.y + w1.y;
            zs.z += w0.z + w1.z; zs.w += w0.w + w1.w;
            float c0 = head == 0 ? w0.x : head == 1 ? w0.y : head == 2 ? w0.z : w0.w;
            float c1 = head == 0 ? w1.x : head == 1 ? w1.y : head == 2 ? w1.z : w1.w;
            acc.x = fmaf(c0, f0a.x, acc.x); acc.x = fmaf(c1, f1a.x, acc.x);
            acc.y = fmaf(c0, f0a.y, acc.y); acc.y = fmaf(c1, f1a.y, acc.y);
            acc.z = fmaf(c0, f0b.x, acc.z); acc.z = fmaf(c1, f1b.x, acc.z);
            acc.w = fmaf(c0, f0b.y, acc.w); acc.w = fmaf(c1, f1b.y, acc.w);
        }
        if (i < end) {
            int s0 = sp[i];
            float4 a0 = elp[s0];
            uint2 u0 = *(const uint2*)&fp[(size_t)s0 * 128 + lane * 4];
            float2 f0a = __half22float2(*(__half2*)&u0.x);
            float2 f0b = __half22float2(*(__half2*)&u0.y);
            float4 w0;
            float t;
            t = a0.x + er4.x; t = t > 0.f ? t : 0.2f * t; w0.x = __expf(t - mx.x);
            t = a0.y + er4.y; t = t > 0.f ? t : 0.2f * t; w0.y = __expf(t - mx.y);
            t = a0.z + er4.z; t = t > 0.f ? t : 0.2f * t; w0.z = __expf(t - mx.z);
            t = a0.w + er4.w; t = t > 0.f ? t : 0.2f * t; w0.w = __expf(t - mx.w);
            zs.x += w0.x; zs.y += w0.y; zs.z += w0.z; zs.w += w0.w;
            float c0 = head == 0 ? w0.x : head == 1 ? w0.y : head == 2 ? w0.z : w0.w;
            acc.x = fmaf(c0, f0a.x, acc.x);
            acc.y = fmaf(c0, f0a.y, acc.y);
            acc.z = fmaf(c0, f0b.x, acc.z);
            acc.w = fmaf(c0, f0b.y, acc.w);
        }
        float zsel = head == 0 ? zs.x : head == 1 ? zs.y : head == 2 ? zs.z : zs.w;
        float inv = 1.f / zsel;
        acc.x *= inv; acc.y *= inv; acc.z *= inv; acc.w *= inv;
        acc.x = acc.x > 0.f ? acc.x : expm1f(acc.x);
        acc.y = acc.y > 0.f ? acc.y : expm1f(acc.y);
        acc.z = acc.z > 0.f ? acc.z : expm1f(acc.z);
        acc.w = acc.w > 0.f ? acc.w : expm1f(acc.w);
    }
    __nv_bfloat16 hv[4], lv[4];
#pragma unroll
    for (int q = 0; q < 4; q++) {
        float v = (&acc.x)[q];
        __nv_bfloat16 hh = __float2bfloat16(v);
        hv[q] = hh;
        lv[q] = __float2bfloat16(v - __bfloat162float(hh));
    }
    *(uint2*)&zh[(size_t)r * 128 + lane * 4] = *(uint2*)hv;
    *(uint2*)&zl[(size_t)r * 128 + lane * 4] = *(uint2*)lv;
}

// ---------------- softmax over meta-paths + combine -----------------------------------
__global__ void k_bsem(const float* __restrict__ wsem, float* __restrict__ bsem) {
    float w0 = wsem[0] / (float)Nn, w1 = wsem[1] / (float)Nn, w2 = wsem[2] / (float)Nn;
    float m = fmaxf(w0, fmaxf(w1, w2));
    float e0 = expf(w0 - m), e1 = expf(w1 - m), e2 = expf(w2 - m);
    float s = e0 + e1 + e2;
    bsem[0] = e0 / s; bsem[1] = e1 / s; bsem[2] = e2 / s;
}

__global__ void k_comb(const __nv_bfloat16* __restrict__ zh, const __nv_bfloat16* __restrict__ zl,
                       const float* __restrict__ bsem, float* __restrict__ out) {
    long i = (long)blockIdx.x * 256 + threadIdx.x;
    if (i >= (long)Nn * 32) return;
    float b[3] = {bsem[0], bsem[1], bsem[2]};
    float4 o = make_float4(0.f, 0.f, 0.f, 0.f);
#pragma unroll
    for (int p = 0; p < 3; p++) {
        size_t base = (size_t)p * Nn * 128 + i * 4;
        uint2 uh = *(const uint2*)&zh[base];
        uint2 ul = *(const uint2*)&zl[base];
        float2 h0 = __bfloat1622float2(*(__nv_bfloat162*)&uh.x);
        float2 h1 = __bfloat1622float2(*(__nv_bfloat162*)&uh.y);
        float2 l0 = __bfloat1622float2(*(__nv_bfloat162*)&ul.x);
        float2 l1 = __bfloat1622float2(*(__nv_bfloat162*)&ul.y);
        o.x = fmaf(b[p], h0.x + l0.x, o.x);
        o.y = fmaf(b[p], h0.y + l0.y, o.y);
        o.z = fmaf(b[p], h1.x + l1.x, o.z);
        o.w = fmaf(b[p], h1.y + l1.y, o.w);
    }
    ((float4*)out)[i] = o;
}

// ---------------- launch ----------------------------------------------------------------
extern "C" void kernel_launch(void* const* d_in, const int* in_sizes, int n_in,
                              void* d_out, int out_size) {
    const float* h      = (const float*)d_in[0];
    const float* cf     = (const float*)d_in[1];
    const float* fa_w1  = (const float*)d_in[2];
    const float* fa_b1  = (const float*)d_in[3];
    const float* fa_w2  = (const float*)d_in[4];
    const float* gat_W  = (const float*)d_in[5];
    const float* attn_l = (const float*)d_in[6];
    const float* attn_r = (const float*)d_in[7];
    const float* sa_w1  = (const float*)d_in[8];
    const float* sa_b1  = (const float*)d_in[9];
    const float* sa_w2  = (const float*)d_in[10];
    const int*   src    = (const int*)d_in[11];
    const int*   dst    = (const int*)d_in[12];
    float* out = (float*)d_out;

    float *pel, *per, *pwsem, *pbsem;
    int *pdeg, *poff, *pcur, *pcsrc;
    __nv_bfloat16 *pbh, *pbl, *pxh, *pxl, *pzh, *pzl;
    __half* pfeat;
    cudaGetSymbolAddress((void**)&pxh, g_x_hi);
    cudaGetSymbolAddress((void**)&pxl, g_x_lo);
    cudaGetSymbolAddress((void**)&pfeat, g_feat);
    cudaGetSymbolAddress((void**)&pzh, g_z_hi);
    cudaGetSymbolAddress((void**)&pzl, g_z_lo);
    cudaGetSymbolAddress((void**)&pel, g_el);
    cudaGetSymbolAddress((void**)&per, g_er);
    cudaGetSymbolAddress((void**)&pdeg, g_deg);
    cudaGetSymbolAddress((void**)&poff, g_off);
    cudaGetSymbolAddress((void**)&pcur, g_cur);
    cudaGetSymbolAddress((void**)&pcsrc, g_csrc);
    cudaGetSymbolAddress((void**)&pbh, g_bt_hi);
    cudaGetSymbolAddress((void**)&pbl, g_bt_lo);
    cudaGetSymbolAddress((void**)&pwsem, g_wsem);
    cudaGetSymbolAddress((void**)&pbsem, g_bsem);

    cudaFuncSetAttribute(k_gemm_feat, cudaFuncAttributeMaxDynamicSharedMemorySize, SMEM_TOT);
    cudaFuncSetAttribute(k_semgemm, cudaFuncAttributeMaxDynamicSharedMemorySize, SMEM_TOT);

    cudaMemsetAsync(pdeg, 0, sizeof(int) * (size_t)Pp * Nn, 0);
    cudaMemsetAsync(pwsem, 0, sizeof(float) * Pp, 0);

    k_wprep<<<(4 * 16384 + 255) / 256, 256>>>(gat_W, sa_w1, pbh, pbl);
    k_featatt<<<(Nn + 7) / 8, 256>>>(h, cf, fa_w1, fa_b1, fa_w2, pxh, pxl);

    dim3 ge4((Ee + 1023) / 1024, Pp);
    k_count<<<ge4, 256>>>(dst, pdeg);

    dim3 gg((Nn + 127) / 128, Pp);
    k_gemm_feat<<<gg, 256, SMEM_TOT>>>(pxh, pxl, pbh, pbl, attn_l, attn_r, pfeat, pel, per);

    k_scan<<<Pp, 1024>>>(pdeg, poff, pcur);
    k_scatter<<<ge4, 256>>>(src, dst, pcur, pcsrc);

    dim3 gn((Nn + 7) / 8, Pp);
    k_gather<<<gn, 256>>>(pcsrc, poff, pel, per, pfeat, pzh, pzl);

    k_semgemm<<<gg, 256, SMEM_TOT>>>(pzh, pzl, pbh + 3 * 16384, pbl + 3 * 16384, sa_b1, sa_w2, pwsem);
    k_bsem<<<1, 1>>>(pwsem, pbsem);
    k_comb<<<(unsigned)(((long)Nn * 32 + 255) / 256), 256>>>(pzh, pzl, pbsem, out);
}

// round 13
// speedup vs baseline: 1.0888x; 1.0531x over previous
#include <cuda_runtime.h>
#include <cuda_fp16.h>
#include <math.h>
#include <stdint.h>

#define Nn 50000
#define Ee 400000
#define Pp 3

// ---------------- scratch (device globals) --------------------------------------
__device__ __align__(16) __half g_x[(size_t)Nn * 128];
__device__ __align__(16) __half g_feat[(size_t)Pp * Nn * 128];
__device__ __align__(16) __half g_z[(size_t)Pp * Nn * 128];
__device__ __align__(16) float g_el[(size_t)Pp * Nn * 4];
__device__ __align__(16) float g_er[(size_t)Pp * Nn * 4];
__device__ int g_deg[(size_t)Pp * Nn];
__device__ int g_off[(size_t)Pp * (Nn + 1)];
__device__ int g_cur[(size_t)Pp * Nn];
__device__ int g_csrc[(size_t)Pp * Ee];
__device__ __align__(16) __half g_bt_hi[4 * 128 * 128];   // [slot][n][k] fp16 hi
__device__ __align__(16) __half g_bt_lo[4 * 128 * 128];   // fp16 lo
__device__ float g_wsem[Pp];
__device__ float g_bsem[Pp];

// ---------------- smem layout ------------------------------------------------------
#define SROW 72
#define TILEB (128 * SROW * 2)
#define S_AUX0 0
#define S_AUX1 512
#define S_RED  1024
#define S_A0   2048
#define S_A1   (S_A0 + TILEB)
#define S_BH   (S_A1 + TILEB)
#define S_BL   (S_BH + TILEB)
#define SMEM_TOT (S_BL + TILEB)       // 75776
#define SDW 132

__device__ __forceinline__ void mma16816(float& d0, float& d1, float& d2, float& d3,
                                         uint32_t a0, uint32_t a1, uint32_t a2, uint32_t a3,
                                         uint32_t b0, uint32_t b1) {
    asm volatile(
        "mma.sync.aligned.m16n8k16.row.col.f32.f16.f16.f32 "
        "{%0,%1,%2,%3}, {%4,%5,%6,%7}, {%8,%9}, {%0,%1,%2,%3};"
        : "+f"(d0), "+f"(d1), "+f"(d2), "+f"(d3)
        : "r"(a0), "r"(a1), "r"(a2), "r"(a3), "r"(b0), "r"(b1));
}

__device__ __forceinline__ void ldsm4(uint32_t& r0, uint32_t& r1, uint32_t& r2,
                                      uint32_t& r3, uint32_t addr) {
    asm volatile("ldmatrix.sync.aligned.m8n8.x4.shared.b16 {%0,%1,%2,%3}, [%4];"
                 : "=r"(r0), "=r"(r1), "=r"(r2), "=r"(r3) : "r"(addr));
}

__device__ __forceinline__ void cpa16(uint32_t dst, const void* src, int sz) {
    asm volatile("cp.async.cg.shared.global [%0], [%1], 16, %2;"
                 :: "r"(dst), "l"(src), "r"(sz));
}
#define CP_COMMIT() asm volatile("cp.async.commit_group;" ::: "memory")
#define CP_WAIT(n)  asm volatile("cp.async.wait_group %0;" :: "n"(n) : "memory")

// fill one A slab (single fp16) via cp.async: 128 rows x 64 cols
__device__ __forceinline__ void fill_A(uint32_t sbase, const __half* a, int n0, int slab,
                                       int tid) {
#pragma unroll
    for (int it = 0; it < 4; it++) {
        int idx = it * 256 + tid;          // 0..1023
        int row = idx >> 3;
        int ch = idx & 7;
        int n = n0 + row;
        int nc = n < Nn ? n : Nn - 1;
        const __half* s = a + (size_t)nc * 128 + slab * 64 + ch * 8;
        uint32_t d = sbase + (uint32_t)((row * SROW + ch * 8) * 2);
        cpa16(d, s, n < Nn ? 16 : 0);
    }
}

__device__ __forceinline__ void fill_B(uint32_t sbase, const __half* bh, const __half* bl,
                                       int slab, int tid) {
#pragma unroll
    for (int it = 0; it < 8; it++) {
        int idx = it * 256 + tid;
        int prec = idx >> 10;
        int rem = idx & 1023;
        int row = rem >> 3;
        int ch = rem & 7;
        const __half* s = (prec ? bl : bh) + (size_t)row * 128 + slab * 64 + ch * 8;
        uint32_t d = sbase + (uint32_t)(prec * TILEB + (row * SROW + ch * 8) * 2);
        cpa16(d, s, 16);
    }
}

// 2-pass MMA over one slab: A x Bh + A x Bl
__device__ __forceinline__ void mma_slab(uint32_t smem_s, uint32_t abase, float d[2][8][4],
                                         int lane, int wid) {
    int warpM = wid & 3, warpN = wid >> 2;
    int grp = lane >> 3, lr = lane & 7;
    uint32_t aA = smem_s + abase +
        (uint32_t)(((warpM * 32 + lr + (grp & 1) * 8) * SROW + (grp >> 1) * 8) * 2);
    uint32_t aB = smem_s + S_BH +
        (uint32_t)(((warpN * 64 + lr + (grp >> 1) * 8) * SROW + (grp & 1) * 8) * 2);
    const uint32_t MT = 16 * SROW * 2;

#pragma unroll
    for (int ks = 0; ks < 4; ks++) {
        uint32_t kb = (uint32_t)(ks * 32);
        uint32_t av[2][4], bb[4][4];
#pragma unroll
        for (int mt = 0; mt < 2; mt++)
            ldsm4(av[mt][0], av[mt][1], av[mt][2], av[mt][3], aA + mt * MT + kb);
#pragma unroll
        for (int np = 0; np < 4; np++)
            ldsm4(bb[np][0], bb[np][1], bb[np][2], bb[np][3], aB + np * MT + kb);
#pragma unroll
        for (int np = 0; np < 4; np++)
#pragma unroll
            for (int mt = 0; mt < 2; mt++) {
                mma16816(d[mt][2 * np][0], d[mt][2 * np][1], d[mt][2 * np][2], d[mt][2 * np][3],
                         av[mt][0], av[mt][1], av[mt][2], av[mt][3], bb[np][0], bb[np][1]);
                mma16816(d[mt][2 * np + 1][0], d[mt][2 * np + 1][1], d[mt][2 * np + 1][2], d[mt][2 * np + 1][3],
                         av[mt][0], av[mt][1], av[mt][2], av[mt][3], bb[np][2], bb[np][3]);
            }
#pragma unroll
        for (int np = 0; np < 4; np++)
            ldsm4(bb[np][0], bb[np][1], bb[np][2], bb[np][3], aB + TILEB + np * MT + kb);
#pragma unroll
        for (int np = 0; np < 4; np++)
#pragma unroll
            for (int mt = 0; mt < 2; mt++) {
                mma16816(d[mt][2 * np][0], d[mt][2 * np][1], d[mt][2 * np][2], d[mt][2 * np][3],
                         av[mt][0], av[mt][1], av[mt][2], av[mt][3], bb[np][0], bb[np][1]);
                mma16816(d[mt][2 * np + 1][0], d[mt][2 * np + 1][1], d[mt][2 * np + 1][2], d[mt][2 * np + 1][3],
                         av[mt][0], av[mt][1], av[mt][2], av[mt][3], bb[np][2], bb[np][3]);
            }
    }
}

// pipelined core: A double-buffered, B refilled between slabs
__device__ __forceinline__ void gemm_core(const __half* __restrict__ a, int n0,
                                          const __half* __restrict__ bth,
                                          const __half* __restrict__ btl,
                                          char* smem, float d[2][8][4]) {
    int tid = threadIdx.x, lane = tid & 31, wid = tid >> 5;
    uint32_t smem_s = (uint32_t)__cvta_generic_to_shared(smem);

    fill_B(smem_s + S_BH, bth, btl, 0, tid);
    fill_A(smem_s + S_A0, a, n0, 0, tid);
    CP_COMMIT();
    fill_A(smem_s + S_A1, a, n0, 1, tid);
    CP_COMMIT();
    CP_WAIT(1);
    __syncthreads();
    mma_slab(smem_s, S_A0, d, lane, wid);
    __syncthreads();
    fill_B(smem_s + S_BH, bth, btl, 1, tid);
    CP_COMMIT();
    CP_WAIT(0);
    __syncthreads();
    mma_slab(smem_s, S_A1, d, lane, wid);
    __syncthreads();
}

__device__ __forceinline__ void stage_d(float* sd, float d[2][8][4], int lane, int wid) {
    int warpM = wid & 3, warpN = wid >> 2;
    int rq = lane >> 2, cq = (lane & 3) * 2;
#pragma unroll
    for (int mt = 0; mt < 2; mt++) {
        int rl0 = warpM * 32 + mt * 16 + rq;
        int rl1 = rl0 + 8;
#pragma unroll
        for (int nt = 0; nt < 8; nt++) {
            int c = warpN * 64 + nt * 8 + cq;
            *(float2*)&sd[rl0 * SDW + c] = make_float2(d[mt][nt][0], d[mt][nt][1]);
            *(float2*)&sd[rl1 * SDW + c] = make_float2(d[mt][nt][2], d[mt][nt][3]);
        }
    }
}

// ---------------- projection GEMM + fused el/er (fp16 feat out) ---------------------
__global__ void __launch_bounds__(256, 2) k_gemm_feat(
    const __half* __restrict__ x, const __half* __restrict__ bth,
    const __half* __restrict__ btl, const float* __restrict__ al,
    const float* __restrict__ ar, __half* __restrict__ feat,
    float* __restrict__ el, float* __restrict__ er) {
    extern __shared__ char smem[];
    int tid = threadIdx.x, lane = tid & 31, wid = tid >> 5;
    int p = blockIdx.y;
    int n0 = blockIdx.x * 128;
    float* sal = (float*)(smem + S_AUX0);
    float* sar = (float*)(smem + S_AUX1);
    if (tid < 128) { sal[tid] = al[p * 128 + tid]; sar[tid] = ar[p * 128 + tid]; }

    float d[2][8][4];
#pragma unroll
    for (int mt = 0; mt < 2; mt++)
#pragma unroll
        for (int nt = 0; nt < 8; nt++)
#pragma unroll
            for (int q = 0; q < 4; q++) d[mt][nt][q] = 0.f;

    gemm_core(x, n0, bth + (size_t)p * 16384, btl + (size_t)p * 16384, smem, d);

    float* sd = (float*)(smem + S_A0);
    stage_d(sd, d, lane, wid);
    __syncthreads();

    int row = tid >> 1, half = tid & 1;
    int n = n0 + row;
    if (n < Nn) {
        float sel[2] = {0.f, 0.f}, ser[2] = {0.f, 0.f};
        __half* o = &feat[((size_t)p * Nn + n) * 128 + half * 64];
#pragma unroll
        for (int q = 0; q < 16; q++) {
            float4 v = *(float4*)&sd[row * SDW + half * 64 + q * 4];
            __half2 h0 = __floats2half2_rn(v.x, v.y);
            __half2 h1 = __floats2half2_rn(v.z, v.w);
            *(uint2*)&o[q * 4] = make_uint2(*(uint32_t*)&h0, *(uint32_t*)&h1);
            int hb = q >> 3;
            int c = half * 64 + q * 4;
            sel[hb] = fmaf(v.x, sal[c + 0], sel[hb]);
            sel[hb] = fmaf(v.y, sal[c + 1], sel[hb]);
            sel[hb] = fmaf(v.z, sal[c + 2], sel[hb]);
            sel[hb] = fmaf(v.w, sal[c + 3], sel[hb]);
            ser[hb] = fmaf(v.x, sar[c + 0], ser[hb]);
            ser[hb] = fmaf(v.y, sar[c + 1], ser[hb]);
            ser[hb] = fmaf(v.z, sar[c + 2], ser[hb]);
            ser[hb] = fmaf(v.w, sar[c + 3], ser[hb]);
        }
        *(float2*)&el[((size_t)p * Nn + n) * 4 + half * 2] = make_float2(sel[0], sel[1]);
        *(float2*)&er[((size_t)p * Nn + n) * 4 + half * 2] = make_float2(ser[0], ser[1]);
    }
}

// ---------------- semantic GEMM + tanh/w2 reduce ------------------------------------
__global__ void __launch_bounds__(256, 2) k_semgemm(
    const __half* __restrict__ z, const __half* __restrict__ bth,
    const __half* __restrict__ btl, const float* __restrict__ b1,
    const float* __restrict__ w2, float* __restrict__ wsem) {
    extern __shared__ char smem[];
    int tid = threadIdx.x, lane = tid & 31, wid = tid >> 5;
    int p = blockIdx.y;
    int n0 = blockIdx.x * 128;
    float* sb1 = (float*)(smem + S_AUX0);
    float* sw2 = (float*)(smem + S_AUX1);
    float* sred = (float*)(smem + S_RED);
    if (tid < 128) { sb1[tid] = b1[tid]; sw2[tid] = w2[tid]; }

    float d[2][8][4];
#pragma unroll
    for (int mt = 0; mt < 2; mt++)
#pragma unroll
        for (int nt = 0; nt < 8; nt++)
#pragma unroll
            for (int q = 0; q < 4; q++) d[mt][nt][q] = 0.f;

    gemm_core(z + (size_t)p * Nn * 128, n0, bth, btl, smem, d);

    float* sd = (float*)(smem + S_A0);
    stage_d(sd, d, lane, wid);
    __syncthreads();

    int row = tid >> 1, half = tid & 1;
    int n = n0 + row;
    float accv = 0.f;
    if (n < Nn) {
#pragma unroll
        for (int q = 0; q < 16; q++) {
            float4 v = *(float4*)&sd[row * SDW + half * 64 + q * 4];
            int c = half * 64 + q * 4;
            accv = fmaf(tanhf(v.x + sb1[c + 0]), sw2[c + 0], accv);
            accv = fmaf(tanhf(v.y + sb1[c + 1]), sw2[c + 1], accv);
            accv = fmaf(tanhf(v.z + sb1[c + 2]), sw2[c + 2], accv);
            accv = fmaf(tanhf(v.w + sb1[c + 3]), sw2[c + 3], accv);
        }
    }
#pragma unroll
    for (int o = 16; o; o >>= 1) accv += __shfl_xor_sync(0xffffffffu, accv, o);
    if (lane == 0) sred[wid] = accv;
    __syncthreads();
    if (tid == 0) {
        float s = 0.f;
#pragma unroll
        for (int i = 0; i < 8; i++) s += sred[i];
        atomicAdd(&wsem[p], s);
    }
}

// ---------------- feature attention: warp per node ----------------------------------
__global__ void k_featatt(const float* __restrict__ h, const float* __restrict__ cf,
                          const float* __restrict__ w1, const float* __restrict__ b1,
                          const float* __restrict__ w2, __half* __restrict__ x) {
    __shared__ float sw1[42 * 16];
    __shared__ float sb1[16], sw2[16];
    __shared__ __align__(16) float sf[8][840];
    __shared__ float ss[8][20];
    int tid = threadIdx.x, wid = tid >> 5, lane = tid & 31;
    for (int i = tid; i < 672; i += 256) sw1[i] = w1[i];
    if (tid < 16) { sb1[tid] = b1[tid]; sw2[tid] = w2[tid]; }
    __syncthreads();
    int n = blockIdx.x * 8 + wid;
    if (n >= Nn) return;

    const float4* fr4 = (const float4*)(cf + (size_t)n * 840);
    float* myf = sf[wid];
    float4* myf4 = (float4*)myf;
    for (int i = lane; i < 210; i += 32) myf4[i] = fr4[i];
    __syncwarp();

    int k = lane & 15;
    for (int j0 = 0; j0 < 20; j0 += 2) {
        int j = j0 + (lane >> 4);
        const float* fj = myf + j * 42;
        float acc = sb1[k];
#pragma unroll
        for (int i = 0; i < 42; i++) acc = fmaf(fj[i], sw1[i * 16 + k], acc);
        float v = tanhf(acc) * sw2[k];
#pragma unroll
        for (int off = 8; off; off >>= 1) v += __shfl_down_sync(0xffffffffu, v, off);
        if (k == 0) ss[wid][j] = v;
    }
    __syncwarp();

    float sc = (lane < 20) ? ss[wid][lane] : -INFINITY;
    float mx = sc;
#pragma unroll
    for (int off = 16; off; off >>= 1) mx = fmaxf(mx, __shfl_xor_sync(0xffffffffu, mx, off));
    float ex = (lane < 20) ? expf(sc - mx) : 0.f;
    float sm = ex;
#pragma unroll
    for (int off = 16; off; off >>= 1) sm += __shfl_xor_sync(0xffffffffu, sm, off);
    float beta = ex / sm;

    float a0 = 0.f, a1 = 0.f;
    for (int j = 0; j < 20; j++) {
        float bj = __shfl_sync(0xffffffffu, beta, j);
        a0 = fmaf(bj, myf[j * 42 + lane], a0);
        if (lane < 10) a1 = fmaf(bj, myf[j * 42 + 32 + lane], a1);
    }
    const float* hr = h + (size_t)n * 86;
    __half* xr = x + (size_t)n * 128;
    for (int i = lane; i < 86; i += 32) xr[i] = __float2half(hr[i]);
    xr[86 + lane] = __float2half(a0);
    if (lane < 10) xr[118 + lane] = __float2half(a1);
}

// ---------------- weight prep: transpose + fp16 hi/lo split ---------------------------
__global__ void k_wprep(const float* __restrict__ gatW, const float* __restrict__ saw1,
                        __half* __restrict__ bh, __half* __restrict__ bl) {
    int idx = blockIdx.x * 256 + threadIdx.x;
    if (idx >= 4 * 16384) return;
    int slot = idx >> 14, rem = idx & 16383;
    int nIdx = rem >> 7, kIdx = rem & 127;
    float v = (slot < 3) ? gatW[slot * 16384 + kIdx * 128 + nIdx] : saw1[kIdx * 128 + nIdx];
    __half hh = __float2half(v);
    bh[idx] = hh;
    bl[idx] = __float2half(v - __half2float(hh));
}

// ---------------- CSR build (4-way ILP atomics) ----------------------------------------
__global__ void k_count(const int* __restrict__ dst, int* __restrict__ deg) {
    int p = blockIdx.y;
    int base = blockIdx.x * 1024 + threadIdx.x;
#pragma unroll
    for (int j = 0; j < 4; j++) {
        int e = base + j * 256;
        if (e < Ee) atomicAdd(&deg[(size_t)p * Nn + dst[(size_t)p * Ee + e]], 1);
    }
}

__global__ void k_scan(const int* __restrict__ deg, int* __restrict__ off,
                       int* __restrict__ cur) {
    int p = blockIdx.x;
    int tid = threadIdx.x, lane = tid & 31, wid = tid >> 5;
    __shared__ int wsum[32];
    __shared__ int carry;
    if (tid == 0) carry = 0;
    __syncthreads();
    for (int base = 0; base < Nn; base += 1024) {
        int i = base + tid;
        int v = (i < Nn) ? deg[(size_t)p * Nn + i] : 0;
        int xv = v;
#pragma unroll
        for (int o = 1; o < 32; o <<= 1) {
            int t = __shfl_up_sync(0xffffffffu, xv, o);
            if (lane >= o) xv += t;
        }
        if (lane == 31) wsum[wid] = xv;
        __syncthreads();
        if (wid == 0) {
            int y = wsum[lane];
#pragma unroll
            for (int o = 1; o < 32; o <<= 1) {
                int t = __shfl_up_sync(0xffffffffu, y, o);
                if (lane >= o) y += t;
            }
            wsum[lane] = y;
        }
        __syncthreads();
        int wpre = (wid == 0) ? 0 : wsum[wid - 1];
        int excl = carry + wpre + xv - v;
        if (i < Nn) {
            off[(size_t)p * (Nn + 1) + i] = excl;
            cur[(size_t)p * Nn + i] = excl;
        }
        __syncthreads();
        if (tid == 1023) carry = excl + v;
        __syncthreads();
    }
    if (tid == 0) off[(size_t)p * (Nn + 1) + Nn] = carry;
}

__global__ void k_scatter(const int* __restrict__ src, const int* __restrict__ dst,
                          int* __restrict__ cur, int* __restrict__ csrc) {
    int p = blockIdx.y;
    int base = blockIdx.x * 1024 + threadIdx.x;
    int ev[4], dv[4], sv[4];
#pragma unroll
    for (int j = 0; j < 4; j++) {
        ev[j] = base + j * 256;
        if (ev[j] < Ee) {
            dv[j] = dst[(size_t)p * Ee + ev[j]];
            sv[j] = src[(size_t)p * Ee + ev[j]];
        }
    }
#pragma unroll
    for (int j = 0; j < 4; j++) {
        if (ev[j] < Ee) {
            int pos = atomicAdd(&cur[(size_t)p * Nn + dv[j]], 1);
            csrc[(size_t)p * Ee + pos] = sv[j];
        }
    }
}

// ---------------- gather aggregation: warp per (p, dst), fp16 feat/z ------------------
__global__ void k_gather(const int* __restrict__ csrc, const int* __restrict__ off,
                         const float* __restrict__ el, const float* __restrict__ er,
                         const __half* __restrict__ feat, __half* __restrict__ z) {
    int p = blockIdx.y;
    int tid = threadIdx.x, wid = tid >> 5, lane = tid & 31;
    int n = blockIdx.x * 8 + wid;
    if (n >= Nn) return;
    long r = (long)p * Nn + n;
    int start = off[(size_t)p * (Nn + 1) + n];
    int end = off[(size_t)p * (Nn + 1) + n + 1];
    float4 acc = make_float4(0.f, 0.f, 0.f, 0.f);
    if (start < end) {
        const int* sp = csrc + (size_t)p * Ee;
        const float4* elp = (const float4*)el + (size_t)p * Nn;
        const __half* fp = feat + (size_t)p * Nn * 128;
        float4 er4 = ((const float4*)er)[r];

        float4 mx = make_float4(-INFINITY, -INFINITY, -INFINITY, -INFINITY);
        for (int i = start + lane; i < end; i += 32) {
            float4 a = elp[sp[i]];
            float vx = a.x + er4.x; vx = vx > 0.f ? vx : 0.2f * vx;
            float vy = a.y + er4.y; vy = vy > 0.f ? vy : 0.2f * vy;
            float vz = a.z + er4.z; vz = vz > 0.f ? vz : 0.2f * vz;
            float vw = a.w + er4.w; vw = vw > 0.f ? vw : 0.2f * vw;
            mx.x = fmaxf(mx.x, vx); mx.y = fmaxf(mx.y, vy);
            mx.z = fmaxf(mx.z, vz); mx.w = fmaxf(mx.w, vw);
        }
#pragma unroll
        for (int o = 16; o; o >>= 1) {
            mx.x = fmaxf(mx.x, __shfl_xor_sync(0xffffffffu, mx.x, o));
            mx.y = fmaxf(mx.y, __shfl_xor_sync(0xffffffffu, mx.y, o));
            mx.z = fmaxf(mx.z, __shfl_xor_sync(0xffffffffu, mx.z, o));
            mx.w = fmaxf(mx.w, __shfl_xor_sync(0xffffffffu, mx.w, o));
        }

        int head = lane >> 3;
        float4 zs = make_float4(0.f, 0.f, 0.f, 0.f);
        int i = start;
        for (; i + 1 < end; i += 2) {
            int s0 = sp[i], s1 = sp[i + 1];
            float4 a0 = elp[s0], a1 = elp[s1];
            uint2 u0 = *(const uint2*)&fp[(size_t)s0 * 128 + lane * 4];
            uint2 u1 = *(const uint2*)&fp[(size_t)s1 * 128 + lane * 4];
            float2 f0a = __half22float2(*(__half2*)&u0.x);
            float2 f0b = __half22float2(*(__half2*)&u0.y);
            float2 f1a = __half22float2(*(__half2*)&u1.x);
            float2 f1b = __half22float2(*(__half2*)&u1.y);
            float4 w0, w1;
            float t;
            t = a0.x + er4.x; t = t > 0.f ? t : 0.2f * t; w0.x = __expf(t - mx.x);
            t = a0.y + er4.y; t = t > 0.f ? t : 0.2f * t; w0.y = __expf(t - mx.y);
            t = a0.z + er4.z; t = t > 0.f ? t : 0.2f * t; w0.z = __expf(t - mx.z);
            t = a0.w + er4.w; t = t > 0.f ? t : 0.2f * t; w0.w = __expf(t - mx.w);
            t = a1.x + er4.x; t = t > 0.f ? t : 0.2f * t; w1.x = __expf(t - mx.x);
            t = a1.y + er4.y; t = t > 0.f ? t : 0.2f * t; w1.y = __expf(t - mx.y);
            t = a1.z + er4.z; t = t > 0.f ? t : 0.2f * t; w1.z = __expf(t - mx.z);
            t = a1.w + er4.w; t = t > 0.f ? t : 0.2f * t; w1.w = __expf(t - mx.w);
            zs.x += w0.x + w1.x; zs.y += w0.y + w1.y;
            zs.z += w0.z + w1.z; zs.w += w0.w + w1.w;
            float c0 = head == 0 ? w0.x : head == 1 ? w0.y : head == 2 ? w0.z : w0.w;
            float c1 = head == 0 ? w1.x : head == 1 ? w1.y : head == 2 ? w1.z : w1.w;
            acc.x = fmaf(c0, f0a.x, acc.x); acc.x = fmaf(c1, f1a.x, acc.x);
            acc.y = fmaf(c0, f0a.y, acc.y); acc.y = fmaf(c1, f1a.y, acc.y);
            acc.z = fmaf(c0, f0b.x, acc.z); acc.z = fmaf(c1, f1b.x, acc.z);
            acc.w = fmaf(c0, f0b.y, acc.w); acc.w = fmaf(c1, f1b.y, acc.w);
        }
        if (i < end) {
            int s0 = sp[i];
            float4 a0 = elp[s0];
            uint2 u0 = *(const uint2*)&fp[(size_t)s0 * 128 + lane * 4];
            float2 f0a = __half22float2(*(__half2*)&u0.x);
            float2 f0b = __half22float2(*(__half2*)&u0.y);
            float4 w0;
            float t;
            t = a0.x + er4.x; t = t > 0.f ? t : 0.2f * t; w0.x = __expf(t - mx.x);
            t = a0.y + er4.y; t = t > 0.f ? t : 0.2f * t; w0.y = __expf(t - mx.y);
            t = a0.z + er4.z; t = t > 0.f ? t : 0.2f * t; w0.z = __expf(t - mx.z);
            t = a0.w + er4.w; t = t > 0.f ? t : 0.2f * t; w0.w = __expf(t - mx.w);
            zs.x += w0.x; zs.y += w0.y; zs.z += w0.z; zs.w += w0.w;
            float c0 = head == 0 ? w0.x : head == 1 ? w0.y : head == 2 ? w0.z : w0.w;
            acc.x = fmaf(c0, f0a.x, acc.x);
            acc.y = fmaf(c0, f0a.y, acc.y);
            acc.z = fmaf(c0, f0b.x, acc.z);
            acc.w = fmaf(c0, f0b.y, acc.w);
        }
        float zsel = head == 0 ? zs.x : head == 1 ? zs.y : head == 2 ? zs.z : zs.w;
        float inv = 1.f / zsel;
        acc.x *= inv; acc.y *= inv; acc.z *= inv; acc.w *= inv;
        acc.x = acc.x > 0.f ? acc.x : expm1f(acc.x);
        acc.y = acc.y > 0.f ? acc.y : expm1f(acc.y);
        acc.z = acc.z > 0.f ? acc.z : expm1f(acc.z);
        acc.w = acc.w > 0.f ? acc.w : expm1f(acc.w);
    }
    __half2 z0 = __floats2half2_rn(acc.x, acc.y);
    __half2 z1 = __floats2half2_rn(acc.z, acc.w);
    *(uint2*)&z[(size_t)r * 128 + lane * 4] = make_uint2(*(uint32_t*)&z0, *(uint32_t*)&z1);
}

// ---------------- softmax over meta-paths + combine -----------------------------------
__global__ void k_bsem(const float* __restrict__ wsem, float* __restrict__ bsem) {
    float w0 = wsem[0] / (float)Nn, w1 = wsem[1] / (float)Nn, w2 = wsem[2] / (float)Nn;
    float m = fmaxf(w0, fmaxf(w1, w2));
    float e0 = expf(w0 - m), e1 = expf(w1 - m), e2 = expf(w2 - m);
    float s = e0 + e1 + e2;
    bsem[0] = e0 / s; bsem[1] = e1 / s; bsem[2] = e2 / s;
}

__global__ void k_comb(const __half* __restrict__ z, const float* __restrict__ bsem,
                       float* __restrict__ out) {
    long i = (long)blockIdx.x * 256 + threadIdx.x;
    if (i >= (long)Nn * 32) return;
    float b[3] = {bsem[0], bsem[1], bsem[2]};
    float4 o = make_float4(0.f, 0.f, 0.f, 0.f);
#pragma unroll
    for (int p = 0; p < 3; p++) {
        size_t base = (size_t)p * Nn * 128 + i * 4;
        uint2 u = *(const uint2*)&z[base];
        float2 a = __half22float2(*(__half2*)&u.x);
        float2 c = __half22float2(*(__half2*)&u.y);
        o.x = fmaf(b[p], a.x, o.x);
        o.y = fmaf(b[p], a.y, o.y);
        o.z = fmaf(b[p], c.x, o.z);
        o.w = fmaf(b[p], c.y, o.w);
    }
    ((float4*)out)[i] = o;
}

// ---------------- launch ----------------------------------------------------------------
extern "C" void kernel_launch(void* const* d_in, const int* in_sizes, int n_in,
                              void* d_out, int out_size) {
    const float* h      = (const float*)d_in[0];
    const float* cf     = (const float*)d_in[1];
    const float* fa_w1  = (const float*)d_in[2];
    const float* fa_b1  = (const float*)d_in[3];
    const float* fa_w2  = (const float*)d_in[4];
    const float* gat_W  = (const float*)d_in[5];
    const float* attn_l = (const float*)d_in[6];
    const float* attn_r = (const float*)d_in[7];
    const float* sa_w1  = (const float*)d_in[8];
    const float* sa_b1  = (const float*)d_in[9];
    const float* sa_w2  = (const float*)d_in[10];
    const int*   src    = (const int*)d_in[11];
    const int*   dst    = (const int*)d_in[12];
    float* out = (float*)d_out;

    float *pel, *per, *pwsem, *pbsem;
    int *pdeg, *poff, *pcur, *pcsrc;
    __half *pbh, *pbl, *px, *pz, *pfeat;
    cudaGetSymbolAddress((void**)&px, g_x);
    cudaGetSymbolAddress((void**)&pfeat, g_feat);
    cudaGetSymbolAddress((void**)&pz, g_z);
    cudaGetSymbolAddress((void**)&pel, g_el);
    cudaGetSymbolAddress((void**)&per, g_er);
    cudaGetSymbolAddress((void**)&pdeg, g_deg);
    cudaGetSymbolAddress((void**)&poff, g_off);
    cudaGetSymbolAddress((void**)&pcur, g_cur);
    cudaGetSymbolAddress((void**)&pcsrc, g_csrc);
    cudaGetSymbolAddress((void**)&pbh, g_bt_hi);
    cudaGetSymbolAddress((void**)&pbl, g_bt_lo);
    cudaGetSymbolAddress((void**)&pwsem, g_wsem);
    cudaGetSymbolAddress((void**)&pbsem, g_bsem);

    cudaFuncSetAttribute(k_gemm_feat, cudaFuncAttributeMaxDynamicSharedMemorySize, SMEM_TOT);
    cudaFuncSetAttribute(k_semgemm, cudaFuncAttributeMaxDynamicSharedMemorySize, SMEM_TOT);

    cudaMemsetAsync(pdeg, 0, sizeof(int) * (size_t)Pp * Nn, 0);
    cudaMemsetAsync(pwsem, 0, sizeof(float) * Pp, 0);

    k_wprep<<<(4 * 16384 + 255) / 256, 256>>>(gat_W, sa_w1, pbh, pbl);
    k_featatt<<<(Nn + 7) / 8, 256>>>(h, cf, fa_w1, fa_b1, fa_w2, px);

    dim3 ge4((Ee + 1023) / 1024, Pp);
    k_count<<<ge4, 256>>>(dst, pdeg);

    dim3 gg((Nn + 127) / 128, Pp);
    k_gemm_feat<<<gg, 256, SMEM_TOT>>>(px, pbh, pbl, attn_l, attn_r, pfeat, pel, per);

    k_scan<<<Pp, 1024>>>(pdeg, poff, pcur);
    k_scatter<<<ge4, 256>>>(src, dst, pcur, pcsrc);

    dim3 gn((Nn + 7) / 8, Pp);
    k_gather<<<gn, 256>>>(pcsrc, poff, pel, per, pfeat, pz);

    k_semgemm<<<gg, 256, SMEM_TOT>>>(pz, pbh + 3 * 16384, pbl + 3 * 16384, sa_b1, sa_w2, pwsem);
    k_bsem<<<1, 1>>>(pwsem, pbsem);
    k_comb<<<(unsigned)(((long)Nn * 32 + 255) / 256), 256>>>(pz, pbsem, out);
}

// round 14
// speedup vs baseline: 1.1399x; 1.0469x over previous
#include <cuda_runtime.h>
#include <cuda_fp16.h>
#include <math.h>
#include <stdint.h>

#define Nn 50000
#define Ee 400000
#define Pp 3

// ---------------- scratch (device globals) --------------------------------------
__device__ __align__(16) __half g_x[(size_t)Nn * 128];
__device__ __align__(16) __half g_feat[(size_t)Pp * Nn * 128];
__device__ __align__(16) __half g_z[(size_t)Pp * Nn * 128];
__device__ __align__(16) float g_el[(size_t)Pp * Nn * 4];
__device__ __align__(16) float g_er[(size_t)Pp * Nn * 4];
__device__ int g_deg[(size_t)Pp * Nn];
__device__ int g_off[(size_t)Pp * (Nn + 1)];
__device__ int g_cur[(size_t)Pp * Nn];
__device__ int g_csrc[(size_t)Pp * Ee];
__device__ __align__(16) __half g_bt[4 * 128 * 128];   // [slot][n][k] fp16 weights^T
__device__ float g_wsem[Pp];
__device__ float g_bsem[Pp];

// ---------------- smem layout ------------------------------------------------------
#define SROW 72
#define TILEB (128 * SROW * 2)
#define S_AUX0 0
#define S_AUX1 512
#define S_RED  1024
#define S_A0   2048
#define S_A1   (S_A0 + TILEB)
#define S_B    (S_A1 + TILEB)
#define SMEM_TOT 69632                 // staging needs 2048 + 128*132*4 = 69632
#define SDW 132

__device__ __forceinline__ void mma16816(float& d0, float& d1, float& d2, float& d3,
                                         uint32_t a0, uint32_t a1, uint32_t a2, uint32_t a3,
                                         uint32_t b0, uint32_t b1) {
    asm volatile(
        "mma.sync.aligned.m16n8k16.row.col.f32.f16.f16.f32 "
        "{%0,%1,%2,%3}, {%4,%5,%6,%7}, {%8,%9}, {%0,%1,%2,%3};"
        : "+f"(d0), "+f"(d1), "+f"(d2), "+f"(d3)
        : "r"(a0), "r"(a1), "r"(a2), "r"(a3), "r"(b0), "r"(b1));
}

__device__ __forceinline__ void ldsm4(uint32_t& r0, uint32_t& r1, uint32_t& r2,
                                      uint32_t& r3, uint32_t addr) {
    asm volatile("ldmatrix.sync.aligned.m8n8.x4.shared.b16 {%0,%1,%2,%3}, [%4];"
                 : "=r"(r0), "=r"(r1), "=r"(r2), "=r"(r3) : "r"(addr));
}

__device__ __forceinline__ void cpa16(uint32_t dst, const void* src, int sz) {
    asm volatile("cp.async.cg.shared.global [%0], [%1], 16, %2;"
                 :: "r"(dst), "l"(src), "r"(sz));
}
#define CP_COMMIT() asm volatile("cp.async.commit_group;" ::: "memory")
#define CP_WAIT(n)  asm volatile("cp.async.wait_group %0;" :: "n"(n) : "memory")

// fill one A slab (fp16) via cp.async: 128 rows x 64 cols
__device__ __forceinline__ void fill_A(uint32_t sbase, const __half* a, int n0, int slab,
                                       int tid) {
#pragma unroll
    for (int it = 0; it < 4; it++) {
        int idx = it * 256 + tid;
        int row = idx >> 3;
        int ch = idx & 7;
        int n = n0 + row;
        int nc = n < Nn ? n : Nn - 1;
        const __half* s = a + (size_t)nc * 128 + slab * 64 + ch * 8;
        uint32_t d = sbase + (uint32_t)((row * SROW + ch * 8) * 2);
        cpa16(d, s, n < Nn ? 16 : 0);
    }
}

__device__ __forceinline__ void fill_B(uint32_t sbase, const __half* b, int slab, int tid) {
#pragma unroll
    for (int it = 0; it < 4; it++) {
        int idx = it * 256 + tid;
        int row = idx >> 3;
        int ch = idx & 7;
        const __half* s = b + (size_t)row * 128 + slab * 64 + ch * 8;
        uint32_t d = sbase + (uint32_t)((row * SROW + ch * 8) * 2);
        cpa16(d, s, 16);
    }
}

// single-pass MMA over one slab
__device__ __forceinline__ void mma_slab(uint32_t smem_s, uint32_t abase, float d[2][8][4],
                                         int lane, int wid) {
    int warpM = wid & 3, warpN = wid >> 2;
    int grp = lane >> 3, lr = lane & 7;
    uint32_t aA = smem_s + abase +
        (uint32_t)(((warpM * 32 + lr + (grp & 1) * 8) * SROW + (grp >> 1) * 8) * 2);
    uint32_t aB = smem_s + S_B +
        (uint32_t)(((warpN * 64 + lr + (grp >> 1) * 8) * SROW + (grp & 1) * 8) * 2);
    const uint32_t MT = 16 * SROW * 2;

#pragma unroll
    for (int ks = 0; ks < 4; ks++) {
        uint32_t kb = (uint32_t)(ks * 32);
        uint32_t av[2][4], bb[4][4];
#pragma unroll
        for (int mt = 0; mt < 2; mt++)
            ldsm4(av[mt][0], av[mt][1], av[mt][2], av[mt][3], aA + mt * MT + kb);
#pragma unroll
        for (int np = 0; np < 4; np++)
            ldsm4(bb[np][0], bb[np][1], bb[np][2], bb[np][3], aB + np * MT + kb);
#pragma unroll
        for (int np = 0; np < 4; np++)
#pragma unroll
            for (int mt = 0; mt < 2; mt++) {
                mma16816(d[mt][2 * np][0], d[mt][2 * np][1], d[mt][2 * np][2], d[mt][2 * np][3],
                         av[mt][0], av[mt][1], av[mt][2], av[mt][3], bb[np][0], bb[np][1]);
                mma16816(d[mt][2 * np + 1][0], d[mt][2 * np + 1][1], d[mt][2 * np + 1][2], d[mt][2 * np + 1][3],
                         av[mt][0], av[mt][1], av[mt][2], av[mt][3], bb[np][2], bb[np][3]);
            }
    }
}

// pipelined core: A double-buffered, B refilled between slabs
__device__ __forceinline__ void gemm_core(const __half* __restrict__ a, int n0,
                                          const __half* __restrict__ bt,
                                          char* smem, float d[2][8][4]) {
    int tid = threadIdx.x, lane = tid & 31, wid = tid >> 5;
    uint32_t smem_s = (uint32_t)__cvta_generic_to_shared(smem);

    fill_B(smem_s + S_B, bt, 0, tid);
    fill_A(smem_s + S_A0, a, n0, 0, tid);
    CP_COMMIT();
    fill_A(smem_s + S_A1, a, n0, 1, tid);
    CP_COMMIT();
    CP_WAIT(1);
    __syncthreads();
    mma_slab(smem_s, S_A0, d, lane, wid);
    __syncthreads();
    fill_B(smem_s + S_B, bt, 1, tid);
    CP_COMMIT();
    CP_WAIT(0);
    __syncthreads();
    mma_slab(smem_s, S_A1, d, lane, wid);
    __syncthreads();
}

__device__ __forceinline__ void stage_d(float* sd, float d[2][8][4], int lane, int wid) {
    int warpM = wid & 3, warpN = wid >> 2;
    int rq = lane >> 2, cq = (lane & 3) * 2;
#pragma unroll
    for (int mt = 0; mt < 2; mt++) {
        int rl0 = warpM * 32 + mt * 16 + rq;
        int rl1 = rl0 + 8;
#pragma unroll
        for (int nt = 0; nt < 8; nt++) {
            int c = warpN * 64 + nt * 8 + cq;
            *(float2*)&sd[rl0 * SDW + c] = make_float2(d[mt][nt][0], d[mt][nt][1]);
            *(float2*)&sd[rl1 * SDW + c] = make_float2(d[mt][nt][2], d[mt][nt][3]);
        }
    }
}

// ---------------- projection GEMM + fused el/er (fp16 feat out) ---------------------
__global__ void __launch_bounds__(256, 2) k_gemm_feat(
    const __half* __restrict__ x, const __half* __restrict__ bt,
    const float* __restrict__ al, const float* __restrict__ ar,
    __half* __restrict__ feat, float* __restrict__ el, float* __restrict__ er) {
    extern __shared__ char smem[];
    int tid = threadIdx.x, lane = tid & 31, wid = tid >> 5;
    int p = blockIdx.y;
    int n0 = blockIdx.x * 128;
    float* sal = (float*)(smem + S_AUX0);
    float* sar = (float*)(smem + S_AUX1);
    if (tid < 128) { sal[tid] = al[p * 128 + tid]; sar[tid] = ar[p * 128 + tid]; }

    float d[2][8][4];
#pragma unroll
    for (int mt = 0; mt < 2; mt++)
#pragma unroll
        for (int nt = 0; nt < 8; nt++)
#pragma unroll
            for (int q = 0; q < 4; q++) d[mt][nt][q] = 0.f;

    gemm_core(x, n0, bt + (size_t)p * 16384, smem, d);

    float* sd = (float*)(smem + S_A0);
    stage_d(sd, d, lane, wid);
    __syncthreads();

    int row = tid >> 1, half = tid & 1;
    int n = n0 + row;
    if (n < Nn) {
        float sel[2] = {0.f, 0.f}, ser[2] = {0.f, 0.f};
        __half* o = &feat[((size_t)p * Nn + n) * 128 + half * 64];
#pragma unroll
        for (int q = 0; q < 16; q++) {
            float4 v = *(float4*)&sd[row * SDW + half * 64 + q * 4];
            __half2 h0 = __floats2half2_rn(v.x, v.y);
            __half2 h1 = __floats2half2_rn(v.z, v.w);
            *(uint2*)&o[q * 4] = make_uint2(*(uint32_t*)&h0, *(uint32_t*)&h1);
            int hb = q >> 3;
            int c = half * 64 + q * 4;
            sel[hb] = fmaf(v.x, sal[c + 0], sel[hb]);
            sel[hb] = fmaf(v.y, sal[c + 1], sel[hb]);
            sel[hb] = fmaf(v.z, sal[c + 2], sel[hb]);
            sel[hb] = fmaf(v.w, sal[c + 3], sel[hb]);
            ser[hb] = fmaf(v.x, sar[c + 0], ser[hb]);
            ser[hb] = fmaf(v.y, sar[c + 1], ser[hb]);
            ser[hb] = fmaf(v.z, sar[c + 2], ser[hb]);
            ser[hb] = fmaf(v.w, sar[c + 3], ser[hb]);
        }
        *(float2*)&el[((size_t)p * Nn + n) * 4 + half * 2] = make_float2(sel[0], sel[1]);
        *(float2*)&er[((size_t)p * Nn + n) * 4 + half * 2] = make_float2(ser[0], ser[1]);
    }
}

// ---------------- semantic GEMM + tanh/w2 reduce ------------------------------------
__global__ void __launch_bounds__(256, 2) k_semgemm(
    const __half* __restrict__ z, const __half* __restrict__ bt,
    const float* __restrict__ b1, const float* __restrict__ w2, float* __restrict__ wsem) {
    extern __shared__ char smem[];
    int tid = threadIdx.x, lane = tid & 31, wid = tid >> 5;
    int p = blockIdx.y;
    int n0 = blockIdx.x * 128;
    float* sb1 = (float*)(smem + S_AUX0);
    float* sw2 = (float*)(smem + S_AUX1);
    float* sred = (float*)(smem + S_RED);
    if (tid < 128) { sb1[tid] = b1[tid]; sw2[tid] = w2[tid]; }

    float d[2][8][4];
#pragma unroll
    for (int mt = 0; mt < 2; mt++)
#pragma unroll
        for (int nt = 0; nt < 8; nt++)
#pragma unroll
            for (int q = 0; q < 4; q++) d[mt][nt][q] = 0.f;

    gemm_core(z + (size_t)p * Nn * 128, n0, bt, smem, d);

    float* sd = (float*)(smem + S_A0);
    stage_d(sd, d, lane, wid);
    __syncthreads();

    int row = tid >> 1, half = tid & 1;
    int n = n0 + row;
    float accv = 0.f;
    if (n < Nn) {
#pragma unroll
        for (int q = 0; q < 16; q++) {
            float4 v = *(float4*)&sd[row * SDW + half * 64 + q * 4];
            int c = half * 64 + q * 4;
            accv = fmaf(tanhf(v.x + sb1[c + 0]), sw2[c + 0], accv);
            accv = fmaf(tanhf(v.y + sb1[c + 1]), sw2[c + 1], accv);
            accv = fmaf(tanhf(v.z + sb1[c + 2]), sw2[c + 2], accv);
            accv = fmaf(tanhf(v.w + sb1[c + 3]), sw2[c + 3], accv);
        }
    }
#pragma unroll
    for (int o = 16; o; o >>= 1) accv += __shfl_xor_sync(0xffffffffu, accv, o);
    if (lane == 0) sred[wid] = accv;
    __syncthreads();
    if (tid == 0) {
        float s = 0.f;
#pragma unroll
        for (int i = 0; i < 8; i++) s += sred[i];
        atomicAdd(&wsem[p], s);
    }
}

// ---------------- feature attention: warp per node ----------------------------------
__global__ void k_featatt(const float* __restrict__ h, const float* __restrict__ cf,
                          const float* __restrict__ w1, const float* __restrict__ b1,
                          const float* __restrict__ w2, __half* __restrict__ x) {
    __shared__ float sw1[42 * 16];
    __shared__ float sb1[16], sw2[16];
    __shared__ __align__(16) float sf[8][840];
    __shared__ float ss[8][20];
    int tid = threadIdx.x, wid = tid >> 5, lane = tid & 31;
    for (int i = tid; i < 672; i += 256) sw1[i] = w1[i];
    if (tid < 16) { sb1[tid] = b1[tid]; sw2[tid] = w2[tid]; }
    __syncthreads();
    int n = blockIdx.x * 8 + wid;
    if (n >= Nn) return;

    const float4* fr4 = (const float4*)(cf + (size_t)n * 840);
    float* myf = sf[wid];
    float4* myf4 = (float4*)myf;
    for (int i = lane; i < 210; i += 32) myf4[i] = fr4[i];
    __syncwarp();

    int k = lane & 15;
    for (int j0 = 0; j0 < 20; j0 += 2) {
        int j = j0 + (lane >> 4);
        const float* fj = myf + j * 42;
        float acc = sb1[k];
#pragma unroll
        for (int i = 0; i < 42; i++) acc = fmaf(fj[i], sw1[i * 16 + k], acc);
        float v = tanhf(acc) * sw2[k];
#pragma unroll
        for (int off = 8; off; off >>= 1) v += __shfl_down_sync(0xffffffffu, v, off);
        if (k == 0) ss[wid][j] = v;
    }
    __syncwarp();

    float sc = (lane < 20) ? ss[wid][lane] : -INFINITY;
    float mx = sc;
#pragma unroll
    for (int off = 16; off; off >>= 1) mx = fmaxf(mx, __shfl_xor_sync(0xffffffffu, mx, off));
    float ex = (lane < 20) ? expf(sc - mx) : 0.f;
    float sm = ex;
#pragma unroll
    for (int off = 16; off; off >>= 1) sm += __shfl_xor_sync(0xffffffffu, sm, off);
    float beta = ex / sm;

    float a0 = 0.f, a1 = 0.f;
    for (int j = 0; j < 20; j++) {
        float bj = __shfl_sync(0xffffffffu, beta, j);
        a0 = fmaf(bj, myf[j * 42 + lane], a0);
        if (lane < 10) a1 = fmaf(bj, myf[j * 42 + 32 + lane], a1);
    }
    const float* hr = h + (size_t)n * 86;
    __half* xr = x + (size_t)n * 128;
    for (int i = lane; i < 86; i += 32) xr[i] = __float2half(hr[i]);
    xr[86 + lane] = __float2half(a0);
    if (lane < 10) xr[118 + lane] = __float2half(a1);
}

// ---------------- weight prep: transpose + fp16 ---------------------------------------
__global__ void k_wprep(const float* __restrict__ gatW, const float* __restrict__ saw1,
                        __half* __restrict__ bt) {
    int idx = blockIdx.x * 256 + threadIdx.x;
    if (idx >= 4 * 16384) return;
    int slot = idx >> 14, rem = idx & 16383;
    int nIdx = rem >> 7, kIdx = rem & 127;
    float v = (slot < 3) ? gatW[slot * 16384 + kIdx * 128 + nIdx] : saw1[kIdx * 128 + nIdx];
    bt[idx] = __float2half(v);
}

// ---------------- CSR build (4-way ILP atomics) ----------------------------------------
__global__ void k_count(const int* __restrict__ dst, int* __restrict__ deg) {
    int p = blockIdx.y;
    int base = blockIdx.x * 1024 + threadIdx.x;
#pragma unroll
    for (int j = 0; j < 4; j++) {
        int e = base + j * 256;
        if (e < Ee) atomicAdd(&deg[(size_t)p * Nn + dst[(size_t)p * Ee + e]], 1);
    }
}

__global__ void k_scan(const int* __restrict__ deg, int* __restrict__ off,
                       int* __restrict__ cur) {
    int p = blockIdx.x;
    int tid = threadIdx.x, lane = tid & 31, wid = tid >> 5;
    __shared__ int wsum[32];
    __shared__ int carry;
    if (tid == 0) carry = 0;
    __syncthreads();
    for (int base = 0; base < Nn; base += 1024) {
        int i = base + tid;
        int v = (i < Nn) ? deg[(size_t)p * Nn + i] : 0;
        int xv = v;
#pragma unroll
        for (int o = 1; o < 32; o <<= 1) {
            int t = __shfl_up_sync(0xffffffffu, xv, o);
            if (lane >= o) xv += t;
        }
        if (lane == 31) wsum[wid] = xv;
        __syncthreads();
        if (wid == 0) {
            int y = wsum[lane];
#pragma unroll
            for (int o = 1; o < 32; o <<= 1) {
                int t = __shfl_up_sync(0xffffffffu, y, o);
                if (lane >= o) y += t;
            }
            wsum[lane] = y;
        }
        __syncthreads();
        int wpre = (wid == 0) ? 0 : wsum[wid - 1];
        int excl = carry + wpre + xv - v;
        if (i < Nn) {
            off[(size_t)p * (Nn + 1) + i] = excl;
            cur[(size_t)p * Nn + i] = excl;
        }
        __syncthreads();
        if (tid == 1023) carry = excl + v;
        __syncthreads();
    }
    if (tid == 0) off[(size_t)p * (Nn + 1) + Nn] = carry;
}

__global__ void k_scatter(const int* __restrict__ src, const int* __restrict__ dst,
                          int* __restrict__ cur, int* __restrict__ csrc) {
    int p = blockIdx.y;
    int base = blockIdx.x * 1024 + threadIdx.x;
    int ev[4], dv[4], sv[4];
#pragma unroll
    for (int j = 0; j < 4; j++) {
        ev[j] = base + j * 256;
        if (ev[j] < Ee) {
            dv[j] = dst[(size_t)p * Ee + ev[j]];
            sv[j] = src[(size_t)p * Ee + ev[j]];
        }
    }
#pragma unroll
    for (int j = 0; j < 4; j++) {
        if (ev[j] < Ee) {
            int pos = atomicAdd(&cur[(size_t)p * Nn + dv[j]], 1);
            csrc[(size_t)p * Ee + pos] = sv[j];
        }
    }
}

// ---------------- gather aggregation: warp per (p, dst), fp16 feat/z ------------------
__global__ void k_gather(const int* __restrict__ csrc, const int* __restrict__ off,
                         const float* __restrict__ el, const float* __restrict__ er,
                         const __half* __restrict__ feat, __half* __restrict__ z) {
    int p = blockIdx.y;
    int tid = threadIdx.x, wid = tid >> 5, lane = tid & 31;
    int n = blockIdx.x * 8 + wid;
    if (n >= Nn) return;
    long r = (long)p * Nn + n;
    int start = off[(size_t)p * (Nn + 1) + n];
    int end = off[(size_t)p * (Nn + 1) + n + 1];
    float4 acc = make_float4(0.f, 0.f, 0.f, 0.f);
    if (start < end) {
        const int* sp = csrc + (size_t)p * Ee;
        const float4* elp = (const float4*)el + (size_t)p * Nn;
        const __half* fp = feat + (size_t)p * Nn * 128;
        float4 er4 = ((const float4*)er)[r];

        float4 mx = make_float4(-INFINITY, -INFINITY, -INFINITY, -INFINITY);
        for (int i = start + lane; i < end; i += 32) {
            float4 a = elp[sp[i]];
            float vx = a.x + er4.x; vx = vx > 0.f ? vx : 0.2f * vx;
            float vy = a.y + er4.y; vy = vy > 0.f ? vy : 0.2f * vy;
            float vz = a.z + er4.z; vz = vz > 0.f ? vz : 0.2f * vz;
            float vw = a.w + er4.w; vw = vw > 0.f ? vw : 0.2f * vw;
            mx.x = fmaxf(mx.x, vx); mx.y = fmaxf(mx.y, vy);
            mx.z = fmaxf(mx.z, vz); mx.w = fmaxf(mx.w, vw);
        }
#pragma unroll
        for (int o = 16; o; o >>= 1) {
            mx.x = fmaxf(mx.x, __shfl_xor_sync(0xffffffffu, mx.x, o));
            mx.y = fmaxf(mx.y, __shfl_xor_sync(0xffffffffu, mx.y, o));
            mx.z = fmaxf(mx.z, __shfl_xor_sync(0xffffffffu, mx.z, o));
            mx.w = fmaxf(mx.w, __shfl_xor_sync(0xffffffffu, mx.w, o));
        }

        int head = lane >> 3;
        float4 zs = make_float4(0.f, 0.f, 0.f, 0.f);
        int i = start;
        for (; i + 1 < end; i += 2) {
            int s0 = sp[i], s1 = sp[i + 1];
            float4 a0 = elp[s0], a1 = elp[s1];
            uint2 u0 = *(const uint2*)&fp[(size_t)s0 * 128 + lane * 4];
            uint2 u1 = *(const uint2*)&fp[(size_t)s1 * 128 + lane * 4];
            float2 f0a = __half22float2(*(__half2*)&u0.x);
            float2 f0b = __half22float2(*(__half2*)&u0.y);
            float2 f1a = __half22float2(*(__half2*)&u1.x);
            float2 f1b = __half22float2(*(__half2*)&u1.y);
            float4 w0, w1;
            float t;
            t = a0.x + er4.x; t = t > 0.f ? t : 0.2f * t; w0.x = __expf(t - mx.x);
            t = a0.y + er4.y; t = t > 0.f ? t : 0.2f * t; w0.y = __expf(t - mx.y);
            t = a0.z + er4.z; t = t > 0.f ? t : 0.2f * t; w0.z = __expf(t - mx.z);
            t = a0.w + er4.w; t = t > 0.f ? t : 0.2f * t; w0.w = __expf(t - mx.w);
            t = a1.x + er4.x; t = t > 0.f ? t : 0.2f * t; w1.x = __expf(t - mx.x);
            t = a1.y + er4.y; t = t > 0.f ? t : 0.2f * t; w1.y = __expf(t - mx.y);
            t = a1.z + er4.z; t = t > 0.f ? t : 0.2f * t; w1.z = __expf(t - mx.z);
            t = a1.w + er4.w; t = t > 0.f ? t : 0.2f * t; w1.w = __expf(t - mx.w);
            zs.x += w0.x + w1.x; zs.y += w0.y + w1.y;
            zs.z += w0.z + w1.z; zs.w += w0.w + w1.w;
            float c0 = head == 0 ? w0.x : head == 1 ? w0.y : head == 2 ? w0.z : w0.w;
            float c1 = head == 0 ? w1.x : head == 1 ? w1.y : head == 2 ? w1.z : w1.w;
            acc.x = fmaf(c0, f0a.x, acc.x); acc.x = fmaf(c1, f1a.x, acc.x);
            acc.y = fmaf(c0, f0a.y, acc.y); acc.y = fmaf(c1, f1a.y, acc.y);
            acc.z = fmaf(c0, f0b.x, acc.z); acc.z = fmaf(c1, f1b.x, acc.z);
            acc.w = fmaf(c0, f0b.y, acc.w); acc.w = fmaf(c1, f1b.y, acc.w);
        }
        if (i < end) {
            int s0 = sp[i];
            float4 a0 = elp[s0];
            uint2 u0 = *(const uint2*)&fp[(size_t)s0 * 128 + lane * 4];
            float2 f0a = __half22float2(*(__half2*)&u0.x);
            float2 f0b = __half22float2(*(__half2*)&u0.y);
            float4 w0;
            float t;
            t = a0.x + er4.x; t = t > 0.f ? t : 0.2f * t; w0.x = __expf(t - mx.x);
            t = a0.y + er4.y; t = t > 0.f ? t : 0.2f * t; w0.y = __expf(t - mx.y);
            t = a0.z + er4.z; t = t > 0.f ? t : 0.2f * t; w0.z = __expf(t - mx.z);
            t = a0.w + er4.w; t = t > 0.f ? t : 0.2f * t; w0.w = __expf(t - mx.w);
            zs.x += w0.x; zs.y += w0.y; zs.z += w0.z; zs.w += w0.w;
            float c0 = head == 0 ? w0.x : head == 1 ? w0.y : head == 2 ? w0.z : w0.w;
            acc.x = fmaf(c0, f0a.x, acc.x);
            acc.y = fmaf(c0, f0a.y, acc.y);
            acc.z = fmaf(c0, f0b.x, acc.z);
            acc.w = fmaf(c0, f0b.y, acc.w);
        }
        float zsel = head == 0 ? zs.x : head == 1 ? zs.y : head == 2 ? zs.z : zs.w;
        float inv = 1.f / zsel;
        acc.x *= inv; acc.y *= inv; acc.z *= inv; acc.w *= inv;
        acc.x = acc.x > 0.f ? acc.x : expm1f(acc.x);
        acc.y = acc.y > 0.f ? acc.y : expm1f(acc.y);
        acc.z = acc.z > 0.f ? acc.z : expm1f(acc.z);
        acc.w = acc.w > 0.f ? acc.w : expm1f(acc.w);
    }
    __half2 z0 = __floats2half2_rn(acc.x, acc.y);
    __half2 z1 = __floats2half2_rn(acc.z, acc.w);
    *(uint2*)&z[(size_t)r * 128 + lane * 4] = make_uint2(*(uint32_t*)&z0, *(uint32_t*)&z1);
}

// ---------------- softmax over meta-paths + combine -----------------------------------
__global__ void k_bsem(const float* __restrict__ wsem, float* __restrict__ bsem) {
    float w0 = wsem[0] / (float)Nn, w1 = wsem[1] / (float)Nn, w2 = wsem[2] / (float)Nn;
    float m = fmaxf(w0, fmaxf(w1, w2));
    float e0 = expf(w0 - m), e1 = expf(w1 - m), e2 = expf(w2 - m);
    float s = e0 + e1 + e2;
    bsem[0] = e0 / s; bsem[1] = e1 / s; bsem[2] = e2 / s;
}

__global__ void k_comb(const __half* __restrict__ z, const float* __restrict__ bsem,
                       float* __restrict__ out) {
    long i = (long)blockIdx.x * 256 + threadIdx.x;
    if (i >= (long)Nn * 32) return;
    float b[3] = {bsem[0], bsem[1], bsem[2]};
    float4 o = make_float4(0.f, 0.f, 0.f, 0.f);
#pragma unroll
    for (int p = 0; p < 3; p++) {
        size_t base = (size_t)p * Nn * 128 + i * 4;
        uint2 u = *(const uint2*)&z[base];
        float2 a = __half22float2(*(__half2*)&u.x);
        float2 c = __half22float2(*(__half2*)&u.y);
        o.x = fmaf(b[p], a.x, o.x);
        o.y = fmaf(b[p], a.y, o.y);
        o.z = fmaf(b[p], c.x, o.z);
        o.w = fmaf(b[p], c.y, o.w);
    }
    ((float4*)out)[i] = o;
}

// ---------------- launch ----------------------------------------------------------------
extern "C" void kernel_launch(void* const* d_in, const int* in_sizes, int n_in,
                              void* d_out, int out_size) {
    const float* h      = (const float*)d_in[0];
    const float* cf     = (const float*)d_in[1];
    const float* fa_w1  = (const float*)d_in[2];
    const float* fa_b1  = (const float*)d_in[3];
    const float* fa_w2  = (const float*)d_in[4];
    const float* gat_W  = (const float*)d_in[5];
    const float* attn_l = (const float*)d_in[6];
    const float* attn_r = (const float*)d_in[7];
    const float* sa_w1  = (const float*)d_in[8];
    const float* sa_b1  = (const float*)d_in[9];
    const float* sa_w2  = (const float*)d_in[10];
    const int*   src    = (const int*)d_in[11];
    const int*   dst    = (const int*)d_in[12];
    float* out = (float*)d_out;

    float *pel, *per, *pwsem, *pbsem;
    int *pdeg, *poff, *pcur, *pcsrc;
    __half *pbt, *px, *pz, *pfeat;
    cudaGetSymbolAddress((void**)&px, g_x);
    cudaGetSymbolAddress((void**)&pfeat, g_feat);
    cudaGetSymbolAddress((void**)&pz, g_z);
    cudaGetSymbolAddress((void**)&pel, g_el);
    cudaGetSymbolAddress((void**)&per, g_er);
    cudaGetSymbolAddress((void**)&pdeg, g_deg);
    cudaGetSymbolAddress((void**)&poff, g_off);
    cudaGetSymbolAddress((void**)&pcur, g_cur);
    cudaGetSymbolAddress((void**)&pcsrc, g_csrc);
    cudaGetSymbolAddress((void**)&pbt, g_bt);
    cudaGetSymbolAddress((void**)&pwsem, g_wsem);
    cudaGetSymbolAddress((void**)&pbsem, g_bsem);

    cudaFuncSetAttribute(k_gemm_feat, cudaFuncAttributeMaxDynamicSharedMemorySize, SMEM_TOT);
    cudaFuncSetAttribute(k_semgemm, cudaFuncAttributeMaxDynamicSharedMemorySize, SMEM_TOT);

    cudaMemsetAsync(pdeg, 0, sizeof(int) * (size_t)Pp * Nn, 0);
    cudaMemsetAsync(pwsem, 0, sizeof(float) * Pp, 0);

    k_wprep<<<(4 * 16384 + 255) / 256, 256>>>(gat_W, sa_w1, pbt);
    k_featatt<<<(Nn + 7) / 8, 256>>>(h, cf, fa_w1, fa_b1, fa_w2, px);

    dim3 ge4((Ee + 1023) / 1024, Pp);
    k_count<<<ge4, 256>>>(dst, pdeg);

    dim3 gg((Nn + 127) / 128, Pp);
    k_gemm_feat<<<gg, 256, SMEM_TOT>>>(px, pbt, attn_l, attn_r, pfeat, pel, per);

    k_scan<<<Pp, 1024>>>(pdeg, poff, pcur);
    k_scatter<<<ge4, 256>>>(src, dst, pcur, pcsrc);

    dim3 gn((Nn + 7) / 8, Pp);
    k_gather<<<gn, 256>>>(pcsrc, poff, pel, per, pfeat, pz);

    k_semgemm<<<gg, 256, SMEM_TOT>>>(pz, pbt + 3 * 16384, sa_b1, sa_w2, pwsem);
    k_bsem<<<1, 1>>>(pwsem, pbsem);
    k_comb<<<(unsigned)(((long)Nn * 32 + 255) / 256), 256>>>(pz, pbsem, out);
}

// round 15
// speedup vs baseline: 1.1432x; 1.0029x over previous
#include <cuda_runtime.h>
#include <cuda_fp16.h>
#include <math.h>
#include <stdint.h>

#define Nn 50000
#define Ee 400000
#define Pp 3

// ---------------- scratch (device globals) --------------------------------------
__device__ __align__(16) __half g_x[(size_t)Nn * 128];
__device__ __align__(16) __half g_feat[(size_t)Pp * Nn * 128];
__device__ __align__(16) __half g_z[(size_t)Pp * Nn * 128];
__device__ __align__(16) float g_el[(size_t)Pp * Nn * 4];
__device__ __align__(16) float g_er[(size_t)Pp * Nn * 4];
__device__ int g_deg[(size_t)Pp * Nn];
__device__ int g_off[(size_t)Pp * (Nn + 1)];
__device__ int g_cur[(size_t)Pp * Nn];
__device__ int g_csrc[(size_t)Pp * Ee];
__device__ __align__(16) __half g_bt[4 * 128 * 128];   // [slot][n][k] fp16 weights^T
__device__ float g_wsem[Pp];
__device__ float g_bsem[Pp];

// ---------------- smem layout: full K=128 tiles ------------------------------------
#define SROW 136                       // halves per padded row (272B, conflict-free)
#define TILEB (128 * SROW * 2)         // 34816
#define S_AUX0 0
#define S_AUX1 512
#define S_RED  1024
#define S_A    2048
#define S_B    (S_A + TILEB)           // 36864
#define SMEM_TOT (S_B + TILEB)         // 71680 (staging needs 69632 <= this)
#define SDW 132

__device__ __forceinline__ void mma16816(float& d0, float& d1, float& d2, float& d3,
                                         uint32_t a0, uint32_t a1, uint32_t a2, uint32_t a3,
                                         uint32_t b0, uint32_t b1) {
    asm volatile(
        "mma.sync.aligned.m16n8k16.row.col.f32.f16.f16.f32 "
        "{%0,%1,%2,%3}, {%4,%5,%6,%7}, {%8,%9}, {%0,%1,%2,%3};"
        : "+f"(d0), "+f"(d1), "+f"(d2), "+f"(d3)
        : "r"(a0), "r"(a1), "r"(a2), "r"(a3), "r"(b0), "r"(b1));
}

__device__ __forceinline__ void ldsm4(uint32_t& r0, uint32_t& r1, uint32_t& r2,
                                      uint32_t& r3, uint32_t addr) {
    asm volatile("ldmatrix.sync.aligned.m8n8.x4.shared.b16 {%0,%1,%2,%3}, [%4];"
                 : "=r"(r0), "=r"(r1), "=r"(r2), "=r"(r3) : "r"(addr));
}

__device__ __forceinline__ void cpa16(uint32_t dst, const void* src, int sz) {
    asm volatile("cp.async.cg.shared.global [%0], [%1], 16, %2;"
                 :: "r"(dst), "l"(src), "r"(sz));
}
#define CP_COMMIT() asm volatile("cp.async.commit_group;" ::: "memory")
#define CP_WAIT(n)  asm volatile("cp.async.wait_group %0;" :: "n"(n) : "memory")

// fill full A tile (128 rows x 128 cols fp16) via cp.async
__device__ __forceinline__ void fill_A(uint32_t sbase, const __half* a, int n0, int tid) {
#pragma unroll
    for (int it = 0; it < 8; it++) {
        int idx = it * 256 + tid;          // 0..2047
        int row = idx >> 4;
        int ch = idx & 15;
        int n = n0 + row;
        int nc = n < Nn ? n : Nn - 1;
        const __half* s = a + (size_t)nc * 128 + ch * 8;
        uint32_t d = sbase + (uint32_t)((row * SROW + ch * 8) * 2);
        cpa16(d, s, n < Nn ? 16 : 0);
    }
}

__device__ __forceinline__ void fill_B(uint32_t sbase, const __half* b, int tid) {
#pragma unroll
    for (int it = 0; it < 8; it++) {
        int idx = it * 256 + tid;
        int row = idx >> 4;
        int ch = idx & 15;
        const __half* s = b + (size_t)row * 128 + ch * 8;
        uint32_t d = sbase + (uint32_t)((row * SROW + ch * 8) * 2);
        cpa16(d, s, 16);
    }
}

// single-phase core: one fill, one sync, 8 uninterrupted k-steps of MMA
__device__ __forceinline__ void gemm_core(const __half* __restrict__ a, int n0,
                                          const __half* __restrict__ bt,
                                          char* smem, float d[2][8][4]) {
    int tid = threadIdx.x, lane = tid & 31, wid = tid >> 5;
    uint32_t smem_s = (uint32_t)__cvta_generic_to_shared(smem);

    fill_A(smem_s + S_A, a, n0, tid);
    fill_B(smem_s + S_B, bt, tid);
    CP_COMMIT();
    CP_WAIT(0);
    __syncthreads();

    int warpM = wid & 3, warpN = wid >> 2;
    int grp = lane >> 3, lr = lane & 7;
    uint32_t aA = smem_s + S_A +
        (uint32_t)(((warpM * 32 + lr + (grp & 1) * 8) * SROW + (grp >> 1) * 8) * 2);
    uint32_t aB = smem_s + S_B +
        (uint32_t)(((warpN * 64 + lr + (grp >> 1) * 8) * SROW + (grp & 1) * 8) * 2);
    const uint32_t MT = 16 * SROW * 2;

#pragma unroll
    for (int ks = 0; ks < 8; ks++) {
        uint32_t kb = (uint32_t)(ks * 32);
        uint32_t av[2][4], bb[4][4];
#pragma unroll
        for (int mt = 0; mt < 2; mt++)
            ldsm4(av[mt][0], av[mt][1], av[mt][2], av[mt][3], aA + mt * MT + kb);
#pragma unroll
        for (int np = 0; np < 4; np++)
            ldsm4(bb[np][0], bb[np][1], bb[np][2], bb[np][3], aB + np * MT + kb);
#pragma unroll
        for (int np = 0; np < 4; np++)
#pragma unroll
            for (int mt = 0; mt < 2; mt++) {
                mma16816(d[mt][2 * np][0], d[mt][2 * np][1], d[mt][2 * np][2], d[mt][2 * np][3],
                         av[mt][0], av[mt][1], av[mt][2], av[mt][3], bb[np][0], bb[np][1]);
                mma16816(d[mt][2 * np + 1][0], d[mt][2 * np + 1][1], d[mt][2 * np + 1][2], d[mt][2 * np + 1][3],
                         av[mt][0], av[mt][1], av[mt][2], av[mt][3], bb[np][2], bb[np][3]);
            }
    }
    __syncthreads();
}

__device__ __forceinline__ void stage_d(float* sd, float d[2][8][4], int lane, int wid) {
    int warpM = wid & 3, warpN = wid >> 2;
    int rq = lane >> 2, cq = (lane & 3) * 2;
#pragma unroll
    for (int mt = 0; mt < 2; mt++) {
        int rl0 = warpM * 32 + mt * 16 + rq;
        int rl1 = rl0 + 8;
#pragma unroll
        for (int nt = 0; nt < 8; nt++) {
            int c = warpN * 64 + nt * 8 + cq;
            *(float2*)&sd[rl0 * SDW + c] = make_float2(d[mt][nt][0], d[mt][nt][1]);
            *(float2*)&sd[rl1 * SDW + c] = make_float2(d[mt][nt][2], d[mt][nt][3]);
        }
    }
}

// ---------------- projection GEMM + fused el/er (fp16 feat out) ---------------------
__global__ void __launch_bounds__(256, 2) k_gemm_feat(
    const __half* __restrict__ x, const __half* __restrict__ bt,
    const float* __restrict__ al, const float* __restrict__ ar,
    __half* __restrict__ feat, float* __restrict__ el, float* __restrict__ er) {
    extern __shared__ char smem[];
    int tid = threadIdx.x, lane = tid & 31, wid = tid >> 5;
    int p = blockIdx.y;
    int n0 = blockIdx.x * 128;
    float* sal = (float*)(smem + S_AUX0);
    float* sar = (float*)(smem + S_AUX1);
    if (tid < 128) { sal[tid] = al[p * 128 + tid]; sar[tid] = ar[p * 128 + tid]; }

    float d[2][8][4];
#pragma unroll
    for (int mt = 0; mt < 2; mt++)
#pragma unroll
        for (int nt = 0; nt < 8; nt++)
#pragma unroll
            for (int q = 0; q < 4; q++) d[mt][nt][q] = 0.f;

    gemm_core(x, n0, bt + (size_t)p * 16384, smem, d);

    float* sd = (float*)(smem + S_A);
    stage_d(sd, d, lane, wid);
    __syncthreads();

    int row = tid >> 1, half = tid & 1;
    int n = n0 + row;
    if (n < Nn) {
        float sel[2] = {0.f, 0.f}, ser[2] = {0.f, 0.f};
        __half* o = &feat[((size_t)p * Nn + n) * 128 + half * 64];
#pragma unroll
        for (int q = 0; q < 16; q++) {
            float4 v = *(float4*)&sd[row * SDW + half * 64 + q * 4];
            __half2 h0 = __floats2half2_rn(v.x, v.y);
            __half2 h1 = __floats2half2_rn(v.z, v.w);
            *(uint2*)&o[q * 4] = make_uint2(*(uint32_t*)&h0, *(uint32_t*)&h1);
            int hb = q >> 3;
            int c = half * 64 + q * 4;
            sel[hb] = fmaf(v.x, sal[c + 0], sel[hb]);
            sel[hb] = fmaf(v.y, sal[c + 1], sel[hb]);
            sel[hb] = fmaf(v.z, sal[c + 2], sel[hb]);
            sel[hb] = fmaf(v.w, sal[c + 3], sel[hb]);
            ser[hb] = fmaf(v.x, sar[c + 0], ser[hb]);
            ser[hb] = fmaf(v.y, sar[c + 1], ser[hb]);
            ser[hb] = fmaf(v.z, sar[c + 2], ser[hb]);
            ser[hb] = fmaf(v.w, sar[c + 3], ser[hb]);
        }
        *(float2*)&el[((size_t)p * Nn + n) * 4 + half * 2] = make_float2(sel[0], sel[1]);
        *(float2*)&er[((size_t)p * Nn + n) * 4 + half * 2] = make_float2(ser[0], ser[1]);
    }
}

// ---------------- semantic GEMM + tanh/w2 reduce ------------------------------------
__global__ void __launch_bounds__(256, 2) k_semgemm(
    const __half* __restrict__ z, const __half* __restrict__ bt,
    const float* __restrict__ b1, const float* __restrict__ w2, float* __restrict__ wsem) {
    extern __shared__ char smem[];
    int tid = threadIdx.x, lane = tid & 31, wid = tid >> 5;
    int p = blockIdx.y;
    int n0 = blockIdx.x * 128;
    float* sb1 = (float*)(smem + S_AUX0);
    float* sw2 = (float*)(smem + S_AUX1);
    float* sred = (float*)(smem + S_RED);
    if (tid < 128) { sb1[tid] = b1[tid]; sw2[tid] = w2[tid]; }

    float d[2][8][4];
#pragma unroll
    for (int mt = 0; mt < 2; mt++)
#pragma unroll
        for (int nt = 0; nt < 8; nt++)
#pragma unroll
            for (int q = 0; q < 4; q++) d[mt][nt][q] = 0.f;

    gemm_core(z + (size_t)p * Nn * 128, n0, bt, smem, d);

    float* sd = (float*)(smem + S_A);
    stage_d(sd, d, lane, wid);
    __syncthreads();

    int row = tid >> 1, half = tid & 1;
    int n = n0 + row;
    float accv = 0.f;
    if (n < Nn) {
#pragma unroll
        for (int q = 0; q < 16; q++) {
            float4 v = *(float4*)&sd[row * SDW + half * 64 + q * 4];
            int c = half * 64 + q * 4;
            accv = fmaf(tanhf(v.x + sb1[c + 0]), sw2[c + 0], accv);
            accv = fmaf(tanhf(v.y + sb1[c + 1]), sw2[c + 1], accv);
            accv = fmaf(tanhf(v.z + sb1[c + 2]), sw2[c + 2], accv);
            accv = fmaf(tanhf(v.w + sb1[c + 3]), sw2[c + 3], accv);
        }
    }
#pragma unroll
    for (int o = 16; o; o >>= 1) accv += __shfl_xor_sync(0xffffffffu, accv, o);
    if (lane == 0) sred[wid] = accv;
    __syncthreads();
    if (tid == 0) {
        float s = 0.f;
#pragma unroll
        for (int i = 0; i < 8; i++) s += sred[i];
        atomicAdd(&wsem[p], s);
    }
}

// ---------------- feature attention: warp per node ----------------------------------
__global__ void k_featatt(const float* __restrict__ h, const float* __restrict__ cf,
                          const float* __restrict__ w1, const float* __restrict__ b1,
                          const float* __restrict__ w2, __half* __restrict__ x) {
    __shared__ float sw1[42 * 16];
    __shared__ float sb1[16], sw2[16];
    __shared__ __align__(16) float sf[8][840];
    __shared__ float ss[8][20];
    int tid = threadIdx.x, wid = tid >> 5, lane = tid & 31;
    for (int i = tid; i < 672; i += 256) sw1[i] = w1[i];
    if (tid < 16) { sb1[tid] = b1[tid]; sw2[tid] = w2[tid]; }
    __syncthreads();
    int n = blockIdx.x * 8 + wid;
    if (n >= Nn) return;

    const float4* fr4 = (const float4*)(cf + (size_t)n * 840);
    float* myf = sf[wid];
    float4* myf4 = (float4*)myf;
    for (int i = lane; i < 210; i += 32) myf4[i] = fr4[i];
    __syncwarp();

    int k = lane & 15;
    for (int j0 = 0; j0 < 20; j0 += 2) {
        int j = j0 + (lane >> 4);
        const float* fj = myf + j * 42;
        float acc = sb1[k];
#pragma unroll
        for (int i = 0; i < 42; i++) acc = fmaf(fj[i], sw1[i * 16 + k], acc);
        float v = tanhf(acc) * sw2[k];
#pragma unroll
        for (int off = 8; off; off >>= 1) v += __shfl_down_sync(0xffffffffu, v, off);
        if (k == 0) ss[wid][j] = v;
    }
    __syncwarp();

    float sc = (lane < 20) ? ss[wid][lane] : -INFINITY;
    float mx = sc;
#pragma unroll
    for (int off = 16; off; off >>= 1) mx = fmaxf(mx, __shfl_xor_sync(0xffffffffu, mx, off));
    float ex = (lane < 20) ? expf(sc - mx) : 0.f;
    float sm = ex;
#pragma unroll
    for (int off = 16; off; off >>= 1) sm += __shfl_xor_sync(0xffffffffu, sm, off);
    float beta = ex / sm;

    float a0 = 0.f, a1 = 0.f;
    for (int j = 0; j < 20; j++) {
        float bj = __shfl_sync(0xffffffffu, beta, j);
        a0 = fmaf(bj, myf[j * 42 + lane], a0);
        if (lane < 10) a1 = fmaf(bj, myf[j * 42 + 32 + lane], a1);
    }
    const float* hr = h + (size_t)n * 86;
    __half* xr = x + (size_t)n * 128;
    for (int i = lane; i < 86; i += 32) xr[i] = __float2half(hr[i]);
    xr[86 + lane] = __float2half(a0);
    if (lane < 10) xr[118 + lane] = __float2half(a1);
}

// ---------------- weight prep: transpose + fp16 ---------------------------------------
__global__ void k_wprep(const float* __restrict__ gatW, const float* __restrict__ saw1,
                        __half* __restrict__ bt) {
    int idx = blockIdx.x * 256 + threadIdx.x;
    if (idx >= 4 * 16384) return;
    int slot = idx >> 14, rem = idx & 16383;
    int nIdx = rem >> 7, kIdx = rem & 127;
    float v = (slot < 3) ? gatW[slot * 16384 + kIdx * 128 + nIdx] : saw1[kIdx * 128 + nIdx];
    bt[idx] = __float2half(v);
}

// ---------------- CSR build (4-way ILP atomics) ----------------------------------------
__global__ void k_count(const int* __restrict__ dst, int* __restrict__ deg) {
    int p = blockIdx.y;
    int base = blockIdx.x * 1024 + threadIdx.x;
#pragma unroll
    for (int j = 0; j < 4; j++) {
        int e = base + j * 256;
        if (e < Ee) atomicAdd(&deg[(size_t)p * Nn + dst[(size_t)p * Ee + e]], 1);
    }
}

__global__ void k_scan(const int* __restrict__ deg, int* __restrict__ off,
                       int* __restrict__ cur) {
    int p = blockIdx.x;
    int tid = threadIdx.x, lane = tid & 31, wid = tid >> 5;
    __shared__ int wsum[32];
    __shared__ int carry;
    if (tid == 0) carry = 0;
    __syncthreads();
    for (int base = 0; base < Nn; base += 1024) {
        int i = base + tid;
        int v = (i < Nn) ? deg[(size_t)p * Nn + i] : 0;
        int xv = v;
#pragma unroll
        for (int o = 1; o < 32; o <<= 1) {
            int t = __shfl_up_sync(0xffffffffu, xv, o);
            if (lane >= o) xv += t;
        }
        if (lane == 31) wsum[wid] = xv;
        __syncthreads();
        if (wid == 0) {
            int y = wsum[lane];
#pragma unroll
            for (int o = 1; o < 32; o <<= 1) {
                int t = __shfl_up_sync(0xffffffffu, y, o);
                if (lane >= o) y += t;
            }
            wsum[lane] = y;
        }
        __syncthreads();
        int wpre = (wid == 0) ? 0 : wsum[wid - 1];
        int excl = carry + wpre + xv - v;
        if (i < Nn) {
            off[(size_t)p * (Nn + 1) + i] = excl;
            cur[(size_t)p * Nn + i] = excl;
        }
        __syncthreads();
        if (tid == 1023) carry = excl + v;
        __syncthreads();
    }
    if (tid == 0) off[(size_t)p * (Nn + 1) + Nn] = carry;
}

__global__ void k_scatter(const int* __restrict__ src, const int* __restrict__ dst,
                          int* __restrict__ cur, int* __restrict__ csrc) {
    int p = blockIdx.y;
    int base = blockIdx.x * 1024 + threadIdx.x;
    int ev[4], dv[4], sv[4];
#pragma unroll
    for (int j = 0; j < 4; j++) {
        ev[j] = base + j * 256;
        if (ev[j] < Ee) {
            dv[j] = dst[(size_t)p * Ee + ev[j]];
            sv[j] = src[(size_t)p * Ee + ev[j]];
        }
    }
#pragma unroll
    for (int j = 0; j < 4; j++) {
        if (ev[j] < Ee) {
            int pos = atomicAdd(&cur[(size_t)p * Nn + dv[j]], 1);
            csrc[(size_t)p * Ee + pos] = sv[j];
        }
    }
}

// ---------------- gather aggregation: warp per (p, dst), fp16 feat/z ------------------
__global__ void k_gather(const int* __restrict__ csrc, const int* __restrict__ off,
                         const float* __restrict__ el, const float* __restrict__ er,
                         const __half* __restrict__ feat, __half* __restrict__ z) {
    int p = blockIdx.y;
    int tid = threadIdx.x, wid = tid >> 5, lane = tid & 31;
    int n = blockIdx.x * 8 + wid;
    if (n >= Nn) return;
    long r = (long)p * Nn + n;
    int start = off[(size_t)p * (Nn + 1) + n];
    int end = off[(size_t)p * (Nn + 1) + n + 1];
    float4 acc = make_float4(0.f, 0.f, 0.f, 0.f);
    if (start < end) {
        const int* sp = csrc + (size_t)p * Ee;
        const float4* elp = (const float4*)el + (size_t)p * Nn;
        const __half* fp = feat + (size_t)p * Nn * 128;
        float4 er4 = ((const float4*)er)[r];

        float4 mx = make_float4(-INFINITY, -INFINITY, -INFINITY, -INFINITY);
        for (int i = start + lane; i < end; i += 32) {
            float4 a = elp[sp[i]];
            float vx = a.x + er4.x; vx = vx > 0.f ? vx : 0.2f * vx;
            float vy = a.y + er4.y; vy = vy > 0.f ? vy : 0.2f * vy;
            float vz = a.z + er4.z; vz = vz > 0.f ? vz : 0.2f * vz;
            float vw = a.w + er4.w; vw = vw > 0.f ? vw : 0.2f * vw;
            mx.x = fmaxf(mx.x, vx); mx.y = fmaxf(mx.y, vy);
            mx.z = fmaxf(mx.z, vz); mx.w = fmaxf(mx.w, vw);
        }
#pragma unroll
        for (int o = 16; o; o >>= 1) {
            mx.x = fmaxf(mx.x, __shfl_xor_sync(0xffffffffu, mx.x, o));
            mx.y = fmaxf(mx.y, __shfl_xor_sync(0xffffffffu, mx.y, o));
            mx.z = fmaxf(mx.z, __shfl_xor_sync(0xffffffffu, mx.z, o));
            mx.w = fmaxf(mx.w, __shfl_xor_sync(0xffffffffu, mx.w, o));
        }

        int head = lane >> 3;
        float4 zs = make_float4(0.f, 0.f, 0.f, 0.f);
        int i = start;
        for (; i + 1 < end; i += 2) {
            int s0 = sp[i], s1 = sp[i + 1];
            float4 a0 = elp[s0], a1 = elp[s1];
            uint2 u0 = *(const uint2*)&fp[(size_t)s0 * 128 + lane * 4];
            uint2 u1 = *(const uint2*)&fp[(size_t)s1 * 128 + lane * 4];
            float2 f0a = __half22float2(*(__half2*)&u0.x);
            float2 f0b = __half22float2(*(__half2*)&u0.y);
            float2 f1a = __half22float2(*(__half2*)&u1.x);
            float2 f1b = __half22float2(*(__half2*)&u1.y);
            float4 w0, w1;
            float t;
            t = a0.x + er4.x; t = t > 0.f ? t : 0.2f * t; w0.x = __expf(t - mx.x);
            t = a0.y + er4.y; t = t > 0.f ? t : 0.2f * t; w0.y = __expf(t - mx.y);
            t = a0.z + er4.z; t = t > 0.f ? t : 0.2f * t; w0.z = __expf(t - mx.z);
            t = a0.w + er4.w; t = t > 0.f ? t : 0.2f * t; w0.w = __expf(t - mx.w);
            t = a1.x + er4.x; t = t > 0.f ? t : 0.2f * t; w1.x = __expf(t - mx.x);
            t = a1.y + er4.y; t = t > 0.f ? t : 0.2f * t; w1.y = __expf(t - mx.y);
            t = a1.z + er4.z; t = t > 0.f ? t : 0.2f * t; w1.z = __expf(t - mx.z);
            t = a1.w + er4.w; t = t > 0.f ? t : 0.2f * t; w1.w = __expf(t - mx.w);
            zs.x += w0.x + w1.x; zs.y += w0.y + w1.y;
            zs.z += w0.z + w1.z; zs.w += w0.w + w1.w;
            float c0 = head == 0 ? w0.x : head == 1 ? w0.y : head == 2 ? w0.z : w0.w;
            float c1 = head == 0 ? w1.x : head == 1 ? w1.y : head == 2 ? w1.z : w1.w;
            acc.x = fmaf(c0, f0a.x, acc.x); acc.x = fmaf(c1, f1a.x, acc.x);
            acc.y = fmaf(c0, f0a.y, acc.y); acc.y = fmaf(c1, f1a.y, acc.y);
            acc.z = fmaf(c0, f0b.x, acc.z); acc.z = fmaf(c1, f1b.x, acc.z);
            acc.w = fmaf(c0, f0b.y, acc.w); acc.w = fmaf(c1, f1b.y, acc.w);
        }
        if (i < end) {
            int s0 = sp[i];
            float4 a0 = elp[s0];
            uint2 u0 = *(const uint2*)&fp[(size_t)s0 * 128 + lane * 4];
            float2 f0a = __half22float2(*(__half2*)&u0.x);
            float2 f0b = __half22float2(*(__half2*)&u0.y);
            float4 w0;
            float t;
            t = a0.x + er4.x; t = t > 0.f ? t : 0.2f * t; w0.x = __expf(t - mx.x);
            t = a0.y + er4.y; t = t > 0.f ? t : 0.2f * t; w0.y = __expf(t - mx.y);
            t = a0.z + er4.z; t = t > 0.f ? t : 0.2f * t; w0.z = __expf(t - mx.z);
            t = a0.w + er4.w; t = t > 0.f ? t : 0.2f * t; w0.w = __expf(t - mx.w);
            zs.x += w0.x; zs.y += w0.y; zs.z += w0.z; zs.w += w0.w;
            float c0 = head == 0 ? w0.x : head == 1 ? w0.y : head == 2 ? w0.z : w0.w;
            acc.x = fmaf(c0, f0a.x, acc.x);
            acc.y = fmaf(c0, f0a.y, acc.y);
            acc.z = fmaf(c0, f0b.x, acc.z);
            acc.w = fmaf(c0, f0b.y, acc.w);
        }
        float zsel = head == 0 ? zs.x : head == 1 ? zs.y : head == 2 ? zs.z : zs.w;
        float inv = 1.f / zsel;
        acc.x *= inv; acc.y *= inv; acc.z *= inv; acc.w *= inv;
        acc.x = acc.x > 0.f ? acc.x : expm1f(acc.x);
        acc.y = acc.y > 0.f ? acc.y : expm1f(acc.y);
        acc.z = acc.z > 0.f ? acc.z : expm1f(acc.z);
        acc.w = acc.w > 0.f ? acc.w : expm1f(acc.w);
    }
    __half2 z0 = __floats2half2_rn(acc.x, acc.y);
    __half2 z1 = __floats2half2_rn(acc.z, acc.w);
    *(uint2*)&z[(size_t)r * 128 + lane * 4] = make_uint2(*(uint32_t*)&z0, *(uint32_t*)&z1);
}

// ---------------- softmax over meta-paths + combine -----------------------------------
__global__ void k_bsem(const float* __restrict__ wsem, float* __restrict__ bsem) {
    float w0 = wsem[0] / (float)Nn, w1 = wsem[1] / (float)Nn, w2 = wsem[2] / (float)Nn;
    float m = fmaxf(w0, fmaxf(w1, w2));
    float e0 = expf(w0 - m), e1 = expf(w1 - m), e2 = expf(w2 - m);
    float s = e0 + e1 + e2;
    bsem[0] = e0 / s; bsem[1] = e1 / s; bsem[2] = e2 / s;
}

__global__ void k_comb(const __half* __restrict__ z, const float* __restrict__ bsem,
                       float* __restrict__ out) {
    long i = (long)blockIdx.x * 256 + threadIdx.x;
    if (i >= (long)Nn * 32) return;
    float b[3] = {bsem[0], bsem[1], bsem[2]};
    float4 o = make_float4(0.f, 0.f, 0.f, 0.f);
#pragma unroll
    for (int p = 0; p < 3; p++) {
        size_t base = (size_t)p * Nn * 128 + i * 4;
        uint2 u = *(const uint2*)&z[base];
        float2 a = __half22float2(*(__half2*)&u.x);
        float2 c = __half22float2(*(__half2*)&u.y);
        o.x = fmaf(b[p], a.x, o.x);
        o.y = fmaf(b[p], a.y, o.y);
        o.z = fmaf(b[p], c.x, o.z);
        o.w = fmaf(b[p], c.y, o.w);
    }
    ((float4*)out)[i] = o;
}

// ---------------- launch ----------------------------------------------------------------
extern "C" void kernel_launch(void* const* d_in, const int* in_sizes, int n_in,
                              void* d_out, int out_size) {
    const float* h      = (const float*)d_in[0];
    const float* cf     = (const float*)d_in[1];
    const float* fa_w1  = (const float*)d_in[2];
    const float* fa_b1  = (const float*)d_in[3];
    const float* fa_w2  = (const float*)d_in[4];
    const float* gat_W  = (const float*)d_in[5];
    const float* attn_l = (const float*)d_in[6];
    const float* attn_r = (const float*)d_in[7];
    const float* sa_w1  = (const float*)d_in[8];
    const float* sa_b1  = (const float*)d_in[9];
    const float* sa_w2  = (const float*)d_in[10];
    const int*   src    = (const int*)d_in[11];
    const int*   dst    = (const int*)d_in[12];
    float* out = (float*)d_out;

    float *pel, *per, *pwsem, *pbsem;
    int *pdeg, *poff, *pcur, *pcsrc;
    __half *pbt, *px, *pz, *pfeat;
    cudaGetSymbolAddress((void**)&px, g_x);
    cudaGetSymbolAddress((void**)&pfeat, g_feat);
    cudaGetSymbolAddress((void**)&pz, g_z);
    cudaGetSymbolAddress((void**)&pel, g_el);
    cudaGetSymbolAddress((void**)&per, g_er);
    cudaGetSymbolAddress((void**)&pdeg, g_deg);
    cudaGetSymbolAddress((void**)&poff, g_off);
    cudaGetSymbolAddress((void**)&pcur, g_cur);
    cudaGetSymbolAddress((void**)&pcsrc, g_csrc);
    cudaGetSymbolAddress((void**)&pbt, g_bt);
    cudaGetSymbolAddress((void**)&pwsem, g_wsem);
    cudaGetSymbolAddress((void**)&pbsem, g_bsem);

    cudaFuncSetAttribute(k_gemm_feat, cudaFuncAttributeMaxDynamicSharedMemorySize, SMEM_TOT);
    cudaFuncSetAttribute(k_semgemm, cudaFuncAttributeMaxDynamicSharedMemorySize, SMEM_TOT);

    cudaMemsetAsync(pdeg, 0, sizeof(int) * (size_t)Pp * Nn, 0);
    cudaMemsetAsync(pwsem, 0, sizeof(float) * Pp, 0);

    k_wprep<<<(4 * 16384 + 255) / 256, 256>>>(gat_W, sa_w1, pbt);
    k_featatt<<<(Nn + 7) / 8, 256>>>(h, cf, fa_w1, fa_b1, fa_w2, px);

    dim3 ge4((Ee + 1023) / 1024, Pp);
    k_count<<<ge4, 256>>>(dst, pdeg);

    dim3 gg((Nn + 127) / 128, Pp);
    k_gemm_feat<<<gg, 256, SMEM_TOT>>>(px, pbt, attn_l, attn_r, pfeat, pel, per);

    k_scan<<<Pp, 1024>>>(pdeg, poff, pcur);
    k_scatter<<<ge4, 256>>>(src, dst, pcur, pcsrc);

    dim3 gn((Nn + 7) / 8, Pp);
    k_gather<<<gn, 256>>>(pcsrc, poff, pel, per, pfeat, pz);

    k_semgemm<<<gg, 256, SMEM_TOT>>>(pz, pbt + 3 * 16384, sa_b1, sa_w2, pwsem);
    k_bsem<<<1, 1>>>(pwsem, pbsem);
    k_comb<<<(unsigned)(((long)Nn * 32 + 255) / 256), 256>>>(pz, pbsem, out);
}

// round 16
// speedup vs baseline: 1.1806x; 1.0328x over previous
#include <cuda_runtime.h>
#include <cuda_fp16.h>
#include <math.h>
#include <stdint.h>

#define Nn 50000
#define Ee 400000
#define Pp 3

// ---------------- scratch (device globals) --------------------------------------
__device__ __align__(16) __half g_x[(size_t)Nn * 128];
__device__ __align__(16) __half g_feat[(size_t)Pp * Nn * 128];
__device__ __align__(16) __half g_z[(size_t)Pp * Nn * 128];
__device__ __align__(16) float g_el[(size_t)Pp * Nn * 4];
__device__ __align__(16) float g_er[(size_t)Pp * Nn * 4];
__device__ int g_deg[(size_t)Pp * Nn];
__device__ int g_off[(size_t)Pp * (Nn + 1)];
__device__ int g_cur[(size_t)Pp * Nn];
__device__ int g_csrc[(size_t)Pp * Ee];
__device__ __align__(16) __half g_bt[4 * 128 * 128];   // [slot][n][k] fp16 weights^T
__device__ float g_wsem[Pp];
__device__ float g_bsem[Pp];

// ---------------- smem layout: full K=128 tiles ------------------------------------
#define SROW 136
#define TILEB (128 * SROW * 2)         // 34816
#define S_AUX0 0
#define S_AUX1 512
#define S_RED  1024
#define S_A    2048
#define S_B    (S_A + TILEB)
#define SMEM_TOT (S_B + TILEB)         // 71680
#define SDW 132

__device__ __forceinline__ void mma16816(float& d0, float& d1, float& d2, float& d3,
                                         uint32_t a0, uint32_t a1, uint32_t a2, uint32_t a3,
                                         uint32_t b0, uint32_t b1) {
    asm volatile(
        "mma.sync.aligned.m16n8k16.row.col.f32.f16.f16.f32 "
        "{%0,%1,%2,%3}, {%4,%5,%6,%7}, {%8,%9}, {%0,%1,%2,%3};"
        : "+f"(d0), "+f"(d1), "+f"(d2), "+f"(d3)
        : "r"(a0), "r"(a1), "r"(a2), "r"(a3), "r"(b0), "r"(b1));
}

__device__ __forceinline__ void ldsm4(uint32_t& r0, uint32_t& r1, uint32_t& r2,
                                      uint32_t& r3, uint32_t addr) {
    asm volatile("ldmatrix.sync.aligned.m8n8.x4.shared.b16 {%0,%1,%2,%3}, [%4];"
                 : "=r"(r0), "=r"(r1), "=r"(r2), "=r"(r3) : "r"(addr));
}

__device__ __forceinline__ void cpa16(uint32_t dst, const void* src, int sz) {
    asm volatile("cp.async.cg.shared.global [%0], [%1], 16, %2;"
                 :: "r"(dst), "l"(src), "r"(sz));
}
#define CP_COMMIT() asm volatile("cp.async.commit_group;" ::: "memory")
#define CP_WAIT(n)  asm volatile("cp.async.wait_group %0;" :: "n"(n) : "memory")

__device__ __forceinline__ void fill_A(uint32_t sbase, const __half* a, int n0, int tid) {
#pragma unroll
    for (int it = 0; it < 8; it++) {
        int idx = it * 256 + tid;
        int row = idx >> 4;
        int ch = idx & 15;
        int n = n0 + row;
        int nc = n < Nn ? n : Nn - 1;
        const __half* s = a + (size_t)nc * 128 + ch * 8;
        uint32_t d = sbase + (uint32_t)((row * SROW + ch * 8) * 2);
        cpa16(d, s, n < Nn ? 16 : 0);
    }
}

__device__ __forceinline__ void fill_B(uint32_t sbase, const __half* b, int tid) {
#pragma unroll
    for (int it = 0; it < 8; it++) {
        int idx = it * 256 + tid;
        int row = idx >> 4;
        int ch = idx & 15;
        const __half* s = b + (size_t)row * 128 + ch * 8;
        uint32_t d = sbase + (uint32_t)((row * SROW + ch * 8) * 2);
        cpa16(d, s, 16);
    }
}

__device__ __forceinline__ void gemm_core(const __half* __restrict__ a, int n0,
                                          const __half* __restrict__ bt,
                                          char* smem, float d[2][8][4]) {
    int tid = threadIdx.x, lane = tid & 31, wid = tid >> 5;
    uint32_t smem_s = (uint32_t)__cvta_generic_to_shared(smem);

    fill_A(smem_s + S_A, a, n0, tid);
    fill_B(smem_s + S_B, bt, tid);
    CP_COMMIT();
    CP_WAIT(0);
    __syncthreads();

    int warpM = wid & 3, warpN = wid >> 2;
    int grp = lane >> 3, lr = lane & 7;
    uint32_t aA = smem_s + S_A +
        (uint32_t)(((warpM * 32 + lr + (grp & 1) * 8) * SROW + (grp >> 1) * 8) * 2);
    uint32_t aB = smem_s + S_B +
        (uint32_t)(((warpN * 64 + lr + (grp >> 1) * 8) * SROW + (grp & 1) * 8) * 2);
    const uint32_t MT = 16 * SROW * 2;

#pragma unroll
    for (int ks = 0; ks < 8; ks++) {
        uint32_t kb = (uint32_t)(ks * 32);
        uint32_t av[2][4], bb[4][4];
#pragma unroll
        for (int mt = 0; mt < 2; mt++)
            ldsm4(av[mt][0], av[mt][1], av[mt][2], av[mt][3], aA + mt * MT + kb);
#pragma unroll
        for (int np = 0; np < 4; np++)
            ldsm4(bb[np][0], bb[np][1], bb[np][2], bb[np][3], aB + np * MT + kb);
#pragma unroll
        for (int np = 0; np < 4; np++)
#pragma unroll
            for (int mt = 0; mt < 2; mt++) {
                mma16816(d[mt][2 * np][0], d[mt][2 * np][1], d[mt][2 * np][2], d[mt][2 * np][3],
                         av[mt][0], av[mt][1], av[mt][2], av[mt][3], bb[np][0], bb[np][1]);
                mma16816(d[mt][2 * np + 1][0], d[mt][2 * np + 1][1], d[mt][2 * np + 1][2], d[mt][2 * np + 1][3],
                         av[mt][0], av[mt][1], av[mt][2], av[mt][3], bb[np][2], bb[np][3]);
            }
    }
    __syncthreads();
}

__device__ __forceinline__ void stage_d(float* sd, float d[2][8][4], int lane, int wid) {
    int warpM = wid & 3, warpN = wid >> 2;
    int rq = lane >> 2, cq = (lane & 3) * 2;
#pragma unroll
    for (int mt = 0; mt < 2; mt++) {
        int rl0 = warpM * 32 + mt * 16 + rq;
        int rl1 = rl0 + 8;
#pragma unroll
        for (int nt = 0; nt < 8; nt++) {
            int c = warpN * 64 + nt * 8 + cq;
            *(float2*)&sd[rl0 * SDW + c] = make_float2(d[mt][nt][0], d[mt][nt][1]);
            *(float2*)&sd[rl1 * SDW + c] = make_float2(d[mt][nt][2], d[mt][nt][3]);
        }
    }
}

// ---------------- projection GEMM + fused el/er (fp16 feat out) ---------------------
__global__ void __launch_bounds__(256, 2) k_gemm_feat(
    const __half* __restrict__ x, const __half* __restrict__ bt,
    const float* __restrict__ al, const float* __restrict__ ar,
    __half* __restrict__ feat, float* __restrict__ el, float* __restrict__ er) {
    extern __shared__ char smem[];
    int tid = threadIdx.x, lane = tid & 31, wid = tid >> 5;
    int p = blockIdx.y;
    int n0 = blockIdx.x * 128;
    float* sal = (float*)(smem + S_AUX0);
    float* sar = (float*)(smem + S_AUX1);
    if (tid < 128) { sal[tid] = al[p * 128 + tid]; sar[tid] = ar[p * 128 + tid]; }

    float d[2][8][4];
#pragma unroll
    for (int mt = 0; mt < 2; mt++)
#pragma unroll
        for (int nt = 0; nt < 8; nt++)
#pragma unroll
            for (int q = 0; q < 4; q++) d[mt][nt][q] = 0.f;

    gemm_core(x, n0, bt + (size_t)p * 16384, smem, d);

    float* sd = (float*)(smem + S_A);
    stage_d(sd, d, lane, wid);
    __syncthreads();

    int row = tid >> 1, half = tid & 1;
    int n = n0 + row;
    if (n < Nn) {
        float sel[2] = {0.f, 0.f}, ser[2] = {0.f, 0.f};
        __half* o = &feat[((size_t)p * Nn + n) * 128 + half * 64];
#pragma unroll
        for (int q = 0; q < 16; q++) {
            float4 v = *(float4*)&sd[row * SDW + half * 64 + q * 4];
            __half2 h0 = __floats2half2_rn(v.x, v.y);
            __half2 h1 = __floats2half2_rn(v.z, v.w);
            *(uint2*)&o[q * 4] = make_uint2(*(uint32_t*)&h0, *(uint32_t*)&h1);
            int hb = q >> 3;
            int c = half * 64 + q * 4;
            sel[hb] = fmaf(v.x, sal[c + 0], sel[hb]);
            sel[hb] = fmaf(v.y, sal[c + 1], sel[hb]);
            sel[hb] = fmaf(v.z, sal[c + 2], sel[hb]);
            sel[hb] = fmaf(v.w, sal[c + 3], sel[hb]);
            ser[hb] = fmaf(v.x, sar[c + 0], ser[hb]);
            ser[hb] = fmaf(v.y, sar[c + 1], ser[hb]);
            ser[hb] = fmaf(v.z, sar[c + 2], ser[hb]);
            ser[hb] = fmaf(v.w, sar[c + 3], ser[hb]);
        }
        *(float2*)&el[((size_t)p * Nn + n) * 4 + half * 2] = make_float2(sel[0], sel[1]);
        *(float2*)&er[((size_t)p * Nn + n) * 4 + half * 2] = make_float2(ser[0], ser[1]);
    }
}

// ---------------- semantic GEMM + tanh/w2 reduce ------------------------------------
__global__ void __launch_bounds__(256, 2) k_semgemm(
    const __half* __restrict__ z, const __half* __restrict__ bt,
    const float* __restrict__ b1, const float* __restrict__ w2, float* __restrict__ wsem) {
    extern __shared__ char smem[];
    int tid = threadIdx.x, lane = tid & 31, wid = tid >> 5;
    int p = blockIdx.y;
    int n0 = blockIdx.x * 128;
    float* sb1 = (float*)(smem + S_AUX0);
    float* sw2 = (float*)(smem + S_AUX1);
    float* sred = (float*)(smem + S_RED);
    if (tid < 128) { sb1[tid] = b1[tid]; sw2[tid] = w2[tid]; }

    float d[2][8][4];
#pragma unroll
    for (int mt = 0; mt < 2; mt++)
#pragma unroll
        for (int nt = 0; nt < 8; nt++)
#pragma unroll
            for (int q = 0; q < 4; q++) d[mt][nt][q] = 0.f;

    gemm_core(z + (size_t)p * Nn * 128, n0, bt, smem, d);

    float* sd = (float*)(smem + S_A);
    stage_d(sd, d, lane, wid);
    __syncthreads();

    int row = tid >> 1, half = tid & 1;
    int n = n0 + row;
    float accv = 0.f;
    if (n < Nn) {
#pragma unroll
        for (int q = 0; q < 16; q++) {
            float4 v = *(float4*)&sd[row * SDW + half * 64 + q * 4];
            int c = half * 64 + q * 4;
            accv = fmaf(tanhf(v.x + sb1[c + 0]), sw2[c + 0], accv);
            accv = fmaf(tanhf(v.y + sb1[c + 1]), sw2[c + 1], accv);
            accv = fmaf(tanhf(v.z + sb1[c + 2]), sw2[c + 2], accv);
            accv = fmaf(tanhf(v.w + sb1[c + 3]), sw2[c + 3], accv);
        }
    }
#pragma unroll
    for (int o = 16; o; o >>= 1) accv += __shfl_xor_sync(0xffffffffu, accv, o);
    if (lane == 0) sred[wid] = accv;
    __syncthreads();
    if (tid == 0) {
        float s = 0.f;
#pragma unroll
        for (int i = 0; i < 8; i++) s += sred[i];
        atomicAdd(&wsem[p], s);
    }
}

// ---------------- feature attention: warp per node ----------------------------------
__global__ void k_featatt(const float* __restrict__ h, const float* __restrict__ cf,
                          const float* __restrict__ w1, const float* __restrict__ b1,
                          const float* __restrict__ w2, __half* __restrict__ x) {
    __shared__ float sw1[42 * 16];
    __shared__ float sb1[16], sw2[16];
    __shared__ __align__(16) float sf[8][840];
    __shared__ float ss[8][20];
    int tid = threadIdx.x, wid = tid >> 5, lane = tid & 31;
    for (int i = tid; i < 672; i += 256) sw1[i] = w1[i];
    if (tid < 16) { sb1[tid] = b1[tid]; sw2[tid] = w2[tid]; }
    __syncthreads();
    int n = blockIdx.x * 8 + wid;
    if (n >= Nn) return;

    const float4* fr4 = (const float4*)(cf + (size_t)n * 840);
    float* myf = sf[wid];
    float4* myf4 = (float4*)myf;
    for (int i = lane; i < 210; i += 32) myf4[i] = fr4[i];
    __syncwarp();

    int k = lane & 15;
    for (int j0 = 0; j0 < 20; j0 += 2) {
        int j = j0 + (lane >> 4);
        const float* fj = myf + j * 42;
        float acc = sb1[k];
#pragma unroll
        for (int i = 0; i < 42; i++) acc = fmaf(fj[i], sw1[i * 16 + k], acc);
        float v = tanhf(acc) * sw2[k];
#pragma unroll
        for (int off = 8; off; off >>= 1) v += __shfl_down_sync(0xffffffffu, v, off);
        if (k == 0) ss[wid][j] = v;
    }
    __syncwarp();

    float sc = (lane < 20) ? ss[wid][lane] : -INFINITY;
    float mx = sc;
#pragma unroll
    for (int off = 16; off; off >>= 1) mx = fmaxf(mx, __shfl_xor_sync(0xffffffffu, mx, off));
    float ex = (lane < 20) ? expf(sc - mx) : 0.f;
    float sm = ex;
#pragma unroll
    for (int off = 16; off; off >>= 1) sm += __shfl_xor_sync(0xffffffffu, sm, off);
    float beta = ex / sm;

    float a0 = 0.f, a1 = 0.f;
    for (int j = 0; j < 20; j++) {
        float bj = __shfl_sync(0xffffffffu, beta, j);
        a0 = fmaf(bj, myf[j * 42 + lane], a0);
        if (lane < 10) a1 = fmaf(bj, myf[j * 42 + 32 + lane], a1);
    }
    const float* hr = h + (size_t)n * 86;
    __half* xr = x + (size_t)n * 128;
    for (int i = lane; i < 86; i += 32) xr[i] = __float2half(hr[i]);
    xr[86 + lane] = __float2half(a0);
    if (lane < 10) xr[118 + lane] = __float2half(a1);
}

// ---------------- weight prep: transpose + fp16 ---------------------------------------
__global__ void k_wprep(const float* __restrict__ gatW, const float* __restrict__ saw1,
                        __half* __restrict__ bt) {
    int idx = blockIdx.x * 256 + threadIdx.x;
    if (idx >= 4 * 16384) return;
    int slot = idx >> 14, rem = idx & 16383;
    int nIdx = rem >> 7, kIdx = rem & 127;
    float v = (slot < 3) ? gatW[slot * 16384 + kIdx * 128 + nIdx] : saw1[kIdx * 128 + nIdx];
    bt[idx] = __float2half(v);
}

// ---------------- CSR build (4-way ILP atomics) ----------------------------------------
__global__ void k_count(const int* __restrict__ dst, int* __restrict__ deg) {
    int p = blockIdx.y;
    int base = blockIdx.x * 1024 + threadIdx.x;
#pragma unroll
    for (int j = 0; j < 4; j++) {
        int e = base + j * 256;
        if (e < Ee) atomicAdd(&deg[(size_t)p * Nn + dst[(size_t)p * Ee + e]], 1);
    }
}

__global__ void k_scan(const int* __restrict__ deg, int* __restrict__ off,
                       int* __restrict__ cur) {
    int p = blockIdx.x;
    int tid = threadIdx.x, lane = tid & 31, wid = tid >> 5;
    __shared__ int wsum[32];
    __shared__ int carry;
    if (tid == 0) carry = 0;
    __syncthreads();
    for (int base = 0; base < Nn; base += 1024) {
        int i = base + tid;
        int v = (i < Nn) ? deg[(size_t)p * Nn + i] : 0;
        int xv = v;
#pragma unroll
        for (int o = 1; o < 32; o <<= 1) {
            int t = __shfl_up_sync(0xffffffffu, xv, o);
            if (lane >= o) xv += t;
        }
        if (lane == 31) wsum[wid] = xv;
        __syncthreads();
        if (wid == 0) {
            int y = wsum[lane];
#pragma unroll
            for (int o = 1; o < 32; o <<= 1) {
                int t = __shfl_up_sync(0xffffffffu, y, o);
                if (lane >= o) y += t;
            }
            wsum[lane] = y;
        }
        __syncthreads();
        int wpre = (wid == 0) ? 0 : wsum[wid - 1];
        int excl = carry + wpre + xv - v;
        if (i < Nn) {
            off[(size_t)p * (Nn + 1) + i] = excl;
            cur[(size_t)p * Nn + i] = excl;
        }
        __syncthreads();
        if (tid == 1023) carry = excl + v;
        __syncthreads();
    }
    if (tid == 0) off[(size_t)p * (Nn + 1) + Nn] = carry;
}

__global__ void k_scatter(const int* __restrict__ src, const int* __restrict__ dst,
                          int* __restrict__ cur, int* __restrict__ csrc) {
    int p = blockIdx.y;
    int base = blockIdx.x * 1024 + threadIdx.x;
    int ev[4], dv[4], sv[4];
#pragma unroll
    for (int j = 0; j < 4; j++) {
        ev[j] = base + j * 256;
        if (ev[j] < Ee) {
            dv[j] = dst[(size_t)p * Ee + ev[j]];
            sv[j] = src[(size_t)p * Ee + ev[j]];
        }
    }
#pragma unroll
    for (int j = 0; j < 4; j++) {
        if (ev[j] < Ee) {
            int pos = atomicAdd(&cur[(size_t)p * Nn + dv[j]], 1);
            csrc[(size_t)p * Ee + pos] = sv[j];
        }
    }
}

// ---------------- gather: warp per (p, dst), single pass (no max subtraction) ---------
__global__ void k_gather(const int* __restrict__ csrc, const int* __restrict__ off,
                         const float* __restrict__ el, const float* __restrict__ er,
                         const __half* __restrict__ feat, __half* __restrict__ z) {
    int p = blockIdx.y;
    int tid = threadIdx.x, wid = tid >> 5, lane = tid & 31;
    int n = blockIdx.x * 8 + wid;
    if (n >= Nn) return;
    long r = (long)p * Nn + n;
    int start = off[(size_t)p * (Nn + 1) + n];
    int end = off[(size_t)p * (Nn + 1) + n + 1];
    float4 acc = make_float4(0.f, 0.f, 0.f, 0.f);
    if (start < end) {
        const int* sp = csrc + (size_t)p * Ee;
        const float4* elp = (const float4*)el + (size_t)p * Nn;
        const __half* fp = feat + (size_t)p * Nn * 128;
        float4 er4 = ((const float4*)er)[r];

        int head = lane >> 3;
        float4 zs = make_float4(0.f, 0.f, 0.f, 0.f);
        int i = start;
        for (; i + 1 < end; i += 2) {
            int s0 = sp[i], s1 = sp[i + 1];
            float4 a0 = elp[s0], a1 = elp[s1];
            uint2 u0 = *(const uint2*)&fp[(size_t)s0 * 128 + lane * 4];
            uint2 u1 = *(const uint2*)&fp[(size_t)s1 * 128 + lane * 4];
            float2 f0a = __half22float2(*(__half2*)&u0.x);
            float2 f0b = __half22float2(*(__half2*)&u0.y);
            float2 f1a = __half22float2(*(__half2*)&u1.x);
            float2 f1b = __half22float2(*(__half2*)&u1.y);
            float4 w0, w1;
            float t;
            t = a0.x + er4.x; t = t > 0.f ? t : 0.2f * t; w0.x = __expf(t);
            t = a0.y + er4.y; t = t > 0.f ? t : 0.2f * t; w0.y = __expf(t);
            t = a0.z + er4.z; t = t > 0.f ? t : 0.2f * t; w0.z = __expf(t);
            t = a0.w + er4.w; t = t > 0.f ? t : 0.2f * t; w0.w = __expf(t);
            t = a1.x + er4.x; t = t > 0.f ? t : 0.2f * t; w1.x = __expf(t);
            t = a1.y + er4.y; t = t > 0.f ? t : 0.2f * t; w1.y = __expf(t);
            t = a1.z + er4.z; t = t > 0.f ? t : 0.2f * t; w1.z = __expf(t);
            t = a1.w + er4.w; t = t > 0.f ? t : 0.2f * t; w1.w = __expf(t);
            zs.x += w0.x + w1.x; zs.y += w0.y + w1.y;
            zs.z += w0.z + w1.z; zs.w += w0.w + w1.w;
            float c0 = head == 0 ? w0.x : head == 1 ? w0.y : head == 2 ? w0.z : w0.w;
            float c1 = head == 0 ? w1.x : head == 1 ? w1.y : head == 2 ? w1.z : w1.w;
            acc.x = fmaf(c0, f0a.x, acc.x); acc.x = fmaf(c1, f1a.x, acc.x);
            acc.y = fmaf(c0, f0a.y, acc.y); acc.y = fmaf(c1, f1a.y, acc.y);
            acc.z = fmaf(c0, f0b.x, acc.z); acc.z = fmaf(c1, f1b.x, acc.z);
            acc.w = fmaf(c0, f0b.y, acc.w); acc.w = fmaf(c1, f1b.y, acc.w);
        }
        if (i < end) {
            int s0 = sp[i];
            float4 a0 = elp[s0];
            uint2 u0 = *(const uint2*)&fp[(size_t)s0 * 128 + lane * 4];
            float2 f0a = __half22float2(*(__half2*)&u0.x);
            float2 f0b = __half22float2(*(__half2*)&u0.y);
            float4 w0;
            float t;
            t = a0.x + er4.x; t = t > 0.f ? t : 0.2f * t; w0.x = __expf(t);
            t = a0.y + er4.y; t = t > 0.f ? t : 0.2f * t; w0.y = __expf(t);
            t = a0.z + er4.z; t = t > 0.f ? t : 0.2f * t; w0.z = __expf(t);
            t = a0.w + er4.w; t = t > 0.f ? t : 0.2f * t; w0.w = __expf(t);
            zs.x += w0.x; zs.y += w0.y; zs.z += w0.z; zs.w += w0.w;
            float c0 = head == 0 ? w0.x : head == 1 ? w0.y : head == 2 ? w0.z : w0.w;
            acc.x = fmaf(c0, f0a.x, acc.x);
            acc.y = fmaf(c0, f0a.y, acc.y);
            acc.z = fmaf(c0, f0b.x, acc.z);
            acc.w = fmaf(c0, f0b.y, acc.w);
        }
        float zsel = head == 0 ? zs.x : head == 1 ? zs.y : head == 2 ? zs.z : zs.w;
        float inv = 1.f / zsel;
        acc.x *= inv; acc.y *= inv; acc.z *= inv; acc.w *= inv;
        acc.x = acc.x > 0.f ? acc.x : expm1f(acc.x);
        acc.y = acc.y > 0.f ? acc.y : expm1f(acc.y);
        acc.z = acc.z > 0.f ? acc.z : expm1f(acc.z);
        acc.w = acc.w > 0.f ? acc.w : expm1f(acc.w);
    }
    __half2 z0 = __floats2half2_rn(acc.x, acc.y);
    __half2 z1 = __floats2half2_rn(acc.z, acc.w);
    *(uint2*)&z[(size_t)r * 128 + lane * 4] = make_uint2(*(uint32_t*)&z0, *(uint32_t*)&z1);
}

// ---------------- softmax over meta-paths + combine -----------------------------------
__global__ void k_bsem(const float* __restrict__ wsem, float* __restrict__ bsem) {
    float w0 = wsem[0] / (float)Nn, w1 = wsem[1] / (float)Nn, w2 = wsem[2] / (float)Nn;
    float m = fmaxf(w0, fmaxf(w1, w2));
    float e0 = expf(w0 - m), e1 = expf(w1 - m), e2 = expf(w2 - m);
    float s = e0 + e1 + e2;
    bsem[0] = e0 / s; bsem[1] = e1 / s; bsem[2] = e2 / s;
}

__global__ void k_comb(const __half* __restrict__ z, const float* __restrict__ bsem,
                       float* __restrict__ out) {
    long i = (long)blockIdx.x * 256 + threadIdx.x;
    if (i >= (long)Nn * 32) return;
    float b[3] = {bsem[0], bsem[1], bsem[2]};
    float4 o = make_float4(0.f, 0.f, 0.f, 0.f);
#pragma unroll
    for (int p = 0; p < 3; p++) {
        size_t base = (size_t)p * Nn * 128 + i * 4;
        uint2 u = *(const uint2*)&z[base];
        float2 a = __half22float2(*(__half2*)&u.x);
        float2 c = __half22float2(*(__half2*)&u.y);
        o.x = fmaf(b[p], a.x, o.x);
        o.y = fmaf(b[p], a.y, o.y);
        o.z = fmaf(b[p], c.x, o.z);
        o.w = fmaf(b[p], c.y, o.w);
    }
    ((float4*)out)[i] = o;
}

// ---------------- launch ----------------------------------------------------------------
extern "C" void kernel_launch(void* const* d_in, const int* in_sizes, int n_in,
                              void* d_out, int out_size) {
    const float* h      = (const float*)d_in[0];
    const float* cf     = (const float*)d_in[1];
    const float* fa_w1  = (const float*)d_in[2];
    const float* fa_b1  = (const float*)d_in[3];
    const float* fa_w2  = (const float*)d_in[4];
    const float* gat_W  = (const float*)d_in[5];
    const float* attn_l = (const float*)d_in[6];
    const float* attn_r = (const float*)d_in[7];
    const float* sa_w1  = (const float*)d_in[8];
    const float* sa_b1  = (const float*)d_in[9];
    const float* sa_w2  = (const float*)d_in[10];
    const int*   src    = (const int*)d_in[11];
    const int*   dst    = (const int*)d_in[12];
    float* out = (float*)d_out;

    float *pel, *per, *pwsem, *pbsem;
    int *pdeg, *poff, *pcur, *pcsrc;
    __half *pbt, *px, *pz, *pfeat;
    cudaGetSymbolAddress((void**)&px, g_x);
    cudaGetSymbolAddress((void**)&pfeat, g_feat);
    cudaGetSymbolAddress((void**)&pz, g_z);
    cudaGetSymbolAddress((void**)&pel, g_el);
    cudaGetSymbolAddress((void**)&per, g_er);
    cudaGetSymbolAddress((void**)&pdeg, g_deg);
    cudaGetSymbolAddress((void**)&poff, g_off);
    cudaGetSymbolAddress((void**)&pcur, g_cur);
    cudaGetSymbolAddress((void**)&pcsrc, g_csrc);
    cudaGetSymbolAddress((void**)&pbt, g_bt);
    cudaGetSymbolAddress((void**)&pwsem, g_wsem);
    cudaGetSymbolAddress((void**)&pbsem, g_bsem);

    cudaFuncSetAttribute(k_gemm_feat, cudaFuncAttributeMaxDynamicSharedMemorySize, SMEM_TOT);
    cudaFuncSetAttribute(k_semgemm, cudaFuncAttributeMaxDynamicSharedMemorySize, SMEM_TOT);

    cudaMemsetAsync(pdeg, 0, sizeof(int) * (size_t)Pp * Nn, 0);
    cudaMemsetAsync(pwsem, 0, sizeof(float) * Pp, 0);

    k_wprep<<<(4 * 16384 + 255) / 256, 256>>>(gat_W, sa_w1, pbt);
    k_featatt<<<(Nn + 7) / 8, 256>>>(h, cf, fa_w1, fa_b1, fa_w2, px);

    dim3 ge4((Ee + 1023) / 1024, Pp);
    k_count<<<ge4, 256>>>(dst, pdeg);

    dim3 gg((Nn + 127) / 128, Pp);
    k_gemm_feat<<<gg, 256, SMEM_TOT>>>(px, pbt, attn_l, attn_r, pfeat, pel, per);

    k_scan<<<Pp, 1024>>>(pdeg, poff, pcur);
    k_scatter<<<ge4, 256>>>(src, dst, pcur, pcsrc);

    dim3 gn((Nn + 7) / 8, Pp);
    k_gather<<<gn, 256>>>(pcsrc, poff, pel, per, pfeat, pz);

    k_semgemm<<<gg, 256, SMEM_TOT>>>(pz, pbt + 3 * 16384, sa_b1, sa_w2, pwsem);
    k_bsem<<<1, 1>>>(pwsem, pbsem);
    k_comb<<<(unsigned)(((long)Nn * 32 + 255) / 256), 256>>>(pz, pbsem, out);
}